// round 10
// baseline (speedup 1.0000x reference)
#include <cuda_runtime.h>
#include <cuda_fp16.h>
#include <cstdint>
#include <math.h>

// ---------------------------------------------------------------------------
// Problem constants
// ---------------------------------------------------------------------------
#define BATCH    4
#define SEQ      2048
#define DMODEL   1024
#define NHEADS   16
#define HDIM     64
#define NEG_INF_F (-1e30f)

#define MROWS   (BATCH * SEQ)       // 8192
#define NQKV    (3 * DMODEL)        // 3072

// ---------------------------------------------------------------------------
// Device scratch (fp16 hi/lo splits)
// ---------------------------------------------------------------------------
__device__ __half g_xhi[(size_t)MROWS * DMODEL];
__device__ __half g_xlo[(size_t)MROWS * DMODEL];
__device__ __half g_ahi[(size_t)MROWS * DMODEL];
__device__ __half g_alo[(size_t)MROWS * DMODEL];
// weights, hi only, transposed [N][K]
__device__ __half g_wqh[(size_t)NQKV * DMODEL];
__device__ __half g_woh[(size_t)DMODEL * DMODEL];
// attention operands: Q (pre-scaled 1/8) hi/lo, K hi/lo in [bh][s][d];
// V hi only, transposed [bh][d][s]
__device__ __half g_qhi[(size_t)BATCH * NHEADS * SEQ * HDIM];
__device__ __half g_qlo[(size_t)BATCH * NHEADS * SEQ * HDIM];
__device__ __half g_khi[(size_t)BATCH * NHEADS * SEQ * HDIM];
__device__ __half g_klo[(size_t)BATCH * NHEADS * SEQ * HDIM];
__device__ __half g_vhi[(size_t)BATCH * NHEADS * HDIM * SEQ];

// ---------------------------------------------------------------------------
// Portable PTX helpers (mma.sync / ldmatrix / cp.async — plain compute_103 OK)
// ---------------------------------------------------------------------------
__device__ __forceinline__ uint32_t smem_u32(const void* p) {
    uint32_t a;
    asm("{ .reg .u64 t; cvta.to.shared.u64 t, %1; cvt.u32.u64 %0, t; }"
        : "=r"(a) : "l"(p));
    return a;
}

__device__ __forceinline__ void ldm_x4(uint32_t* r, uint32_t addr) {
    asm volatile("ldmatrix.sync.aligned.m8n8.x4.shared.b16 {%0,%1,%2,%3}, [%4];"
                 : "=r"(r[0]), "=r"(r[1]), "=r"(r[2]), "=r"(r[3]) : "r"(addr));
}

__device__ __forceinline__ void mma16816(float* d, const uint32_t* a, const uint32_t* b) {
    asm volatile(
        "mma.sync.aligned.m16n8k16.row.col.f32.f16.f16.f32 "
        "{%0,%1,%2,%3}, {%4,%5,%6,%7}, {%8,%9}, {%0,%1,%2,%3};"
        : "+f"(d[0]), "+f"(d[1]), "+f"(d[2]), "+f"(d[3])
        : "r"(a[0]), "r"(a[1]), "r"(a[2]), "r"(a[3]), "r"(b[0]), "r"(b[1]));
}

__device__ __forceinline__ void cp_async16(uint32_t saddr, const void* gptr) {
    asm volatile("cp.async.cg.shared.global [%0], [%1], 16;"
                 :: "r"(saddr), "l"(gptr));
}
__device__ __forceinline__ void cp_commit() {
    asm volatile("cp.async.commit_group;");
}
template<int N> __device__ __forceinline__ void cp_wait() {
    asm volatile("cp.async.wait_group %0;" :: "n"(N));
}

// pack two fp32 into f16x2: high half = hi_val, low half = lo_val
__device__ __forceinline__ uint32_t cvt_f16x2(float hi_val, float lo_val) {
    uint32_t r;
    asm("cvt.rn.f16x2.f32 %0, %1, %2;" : "=r"(r) : "f"(hi_val), "f"(lo_val));
    return r;
}
__device__ __forceinline__ float f16x2_lo(uint32_t v) {
    __half2 t = *(__half2*)&v; return __half2float(t.x);
}
__device__ __forceinline__ float f16x2_hi(uint32_t v) {
    __half2 t = *(__half2*)&v; return __half2float(t.y);
}

// ---------------------------------------------------------------------------
// Conversion: x fp32 -> (hi, lo) fp16 split
// ---------------------------------------------------------------------------
__global__ __launch_bounds__(256) void convert_split_kernel(
    const float* __restrict__ src, int n4)
{
    int i = blockIdx.x * 256 + threadIdx.x;
    if (i >= n4) return;
    float4 v = ((const float4*)src)[i];
    __half h0 = __float2half_rn(v.x);
    __half h1 = __float2half_rn(v.y);
    __half h2 = __float2half_rn(v.z);
    __half h3 = __float2half_rn(v.w);
    __half2 ph0; ph0.x = h0; ph0.y = h1;
    __half2 ph1; ph1.x = h2; ph1.y = h3;
    __half2 pl0;
    pl0.x = __float2half_rn(v.x - __half2float(h0));
    pl0.y = __float2half_rn(v.y - __half2float(h1));
    __half2 pl1;
    pl1.x = __float2half_rn(v.z - __half2float(h2));
    pl1.y = __float2half_rn(v.w - __half2float(h3));
    ((__half2*)g_xhi)[2 * i]     = ph0;
    ((__half2*)g_xhi)[2 * i + 1] = ph1;
    ((__half2*)g_xlo)[2 * i]     = pl0;
    ((__half2*)g_xlo)[2 * i + 1] = pl1;
}

// W [K x N] fp32 -> transposed [N x K] fp16 hi only
__global__ __launch_bounds__(256) void transpose_split_kernel(
    const float* __restrict__ src, int sel, int N)
{
    __shared__ float tile[32][33];
    const int K = DMODEL;
    __half* hi = (sel == 0) ? g_wqh : g_woh;

    int tx = threadIdx.x;
    int ty = threadIdx.y;
    int n0 = blockIdx.x * 32;
    int k0 = blockIdx.y * 32;

#pragma unroll
    for (int i = 0; i < 4; i++)
        tile[ty + 8 * i][tx] = src[(size_t)(k0 + ty + 8 * i) * N + n0 + tx];
    __syncthreads();
#pragma unroll
    for (int i = 0; i < 4; i++) {
        float v = tile[tx][ty + 8 * i];
        hi[(size_t)(n0 + ty + 8 * i) * K + k0 + tx] = __float2half_rn(v);
    }
}

// ---------------------------------------------------------------------------
// mma.sync GEMM, 2-term fp16: D = (Ah + Al) * Bh  (= A * Bh exactly).
// CTA tile 128 x 256, 8 warps 2x4, warp tile 64 x 64.  K-chunk 64.
// 2-stage cp.async double buffer; 1 CTA/SM (reg+smem bound).
// Stage = Ah(128x64) + Al(128x64) + Bh(256x64) fp16, 144B padded rows
//       = 73728 B; 2 stages = 147456 B.
// MODE 0: epilogue -> q/k hi/lo [bh][s][d], v hi transposed [bh][d][s].
// MODE 1: plain fp32 store into Cout.
// ---------------------------------------------------------------------------
#define ROWB 144
#define OFF_AL   18432                    // 128*144
#define OFF_BH   36864                    // 2*128*144
#define STAGE_BYTES 73728                 // OFF_BH + 256*144
#define GEMM_SMEM_BYTES (2 * STAGE_BYTES) // 147456

template<int MODE>
__global__ __launch_bounds__(256, 1) void mma_gemm_kernel(float* __restrict__ Cout)
{
    extern __shared__ char smem[];
    const uint32_t sbase = smem_u32(smem);

    const int tid  = threadIdx.x;
    const int wid  = tid >> 5;
    const int lane = tid & 31;
    const int wm   = wid >> 2;          // 0..1 -> m offset wm*64
    const int wn   = wid & 3;           // 0..3 -> n offset wn*64
    const int m0   = blockIdx.y * 128;
    const int n0   = blockIdx.x * 256;

    const __half* Ahi = (MODE == 0) ? g_xhi : g_ahi;
    const __half* Alo = (MODE == 0) ? g_xlo : g_alo;
    const __half* Bhi = (MODE == 0) ? g_wqh : g_woh;

    const uint4* A4h = (const uint4*)Ahi;   // row stride = 128 uint4
    const uint4* A4l = (const uint4*)Alo;
    const uint4* B4h = (const uint4*)Bhi;

    float acc[4][8][4];
#pragma unroll
    for (int i = 0; i < 4; i++)
#pragma unroll
        for (int j = 0; j < 8; j++)
#pragma unroll
            for (int c = 0; c < 4; c++) acc[i][j][c] = 0.f;

    const int a_row = wm * 64 + (lane & 15);
    const int a_col = (lane >> 4) * 8;
    const int b_row = wn * 64 + (lane & 7) + (lane >> 4) * 8;
    const int b_col = ((lane >> 3) & 1) * 8;

    // staging: Ah 1024 uint4 (4 iters), Al 1024 (4 iters), Bh 2048 (8 iters)
    auto prefetch = [&](int kc, int stage) {
        const uint32_t sb = sbase + stage * STAGE_BYTES;
#pragma unroll
        for (int it = 0; it < 4; it++) {
            int e   = tid + it * 256;
            int row = e >> 3;
            int seg = e & 7;
            uint32_t soff = sb + (uint32_t)(row * ROWB + seg * 16);
            size_t aidx = (size_t)(m0 + row) * 128 + kc * 8 + seg;
            cp_async16(soff,          A4h + aidx);
            cp_async16(soff + OFF_AL, A4l + aidx);
        }
#pragma unroll
        for (int it = 0; it < 8; it++) {
            int e   = tid + it * 256;
            int row = e >> 3;            // 0..255
            int seg = e & 7;
            uint32_t soff = sb + OFF_BH + (uint32_t)(row * ROWB + seg * 16);
            size_t bidx = (size_t)(n0 + row) * 128 + kc * 8 + seg;
            cp_async16(soff, B4h + bidx);
        }
        cp_commit();
    };

    prefetch(0, 0);

    for (int kc = 0; kc < 16; kc++) {
        const int cur = kc & 1;
        if (kc + 1 < 16) {
            prefetch(kc + 1, cur ^ 1);
            cp_wait<1>();
        } else {
            cp_wait<0>();
        }
        __syncthreads();

        const uint32_t stg = sbase + cur * STAGE_BYTES;
#pragma unroll
        for (int ks = 0; ks < 4; ks++) {
            uint32_t a_addr = stg + (uint32_t)(a_row * ROWB + (ks * 16 + a_col) * 2);
            uint32_t b_addr = stg + OFF_BH +
                              (uint32_t)(b_row * ROWB + (ks * 16 + b_col) * 2);

            uint32_t af[4][4];
            uint32_t bh[8][2];

#pragma unroll
            for (int mi = 0; mi < 4; mi++)
                ldm_x4(af[mi], a_addr + mi * 16 * ROWB);
#pragma unroll
            for (int np = 0; np < 4; np++) {
                uint32_t r[4];
                ldm_x4(r, b_addr + np * 16 * ROWB);
                bh[np * 2][0] = r[0]; bh[np * 2][1] = r[1];
                bh[np * 2 + 1][0] = r[2]; bh[np * 2 + 1][1] = r[3];
            }

            // Ah * Bh
#pragma unroll
            for (int mi = 0; mi < 4; mi++)
#pragma unroll
                for (int ni = 0; ni < 8; ni++)
                    mma16816(acc[mi][ni], af[mi], bh[ni]);
            // Al * Bh (reload A frags as lo)
#pragma unroll
            for (int mi = 0; mi < 4; mi++)
                ldm_x4(af[mi], a_addr + OFF_AL + mi * 16 * ROWB);
#pragma unroll
            for (int mi = 0; mi < 4; mi++)
#pragma unroll
                for (int ni = 0; ni < 8; ni++)
                    mma16816(acc[mi][ni], af[mi], bh[ni]);
        }
        __syncthreads();
    }

    const int er = lane >> 2;
    const int ec = (lane & 3) * 2;
#pragma unroll
    for (int mi = 0; mi < 4; mi++) {
#pragma unroll
        for (int rr = 0; rr < 2; rr++) {
            int m = m0 + wm * 64 + mi * 16 + er + rr * 8;
            int b = m >> 11;
            int s = m & 2047;
#pragma unroll
            for (int ni = 0; ni < 8; ni++) {
#pragma unroll
                for (int cc = 0; cc < 2; cc++) {
                    int n = n0 + wn * 64 + ni * 8 + ec + cc;
                    float v = acc[mi][ni][rr * 2 + cc];
                    if (MODE == 0) {
                        int t = n >> 10;
                        int h = (n >> 6) & 15;
                        int d = n & 63;
                        if (t == 0) v *= 0.125f;   // fold 1/sqrt(hd) into Q
                        __half hv = __float2half_rn(v);
                        int bh_i = b * NHEADS + h;
                        if (t == 2) {
                            g_vhi[((size_t)bh_i * HDIM + d) * SEQ + s] = hv;
                        } else {
                            __half lv = __float2half_rn(v - __half2float(hv));
                            size_t o = ((size_t)bh_i * SEQ + s) * HDIM + d;
                            if (t == 0) { g_qhi[o] = hv; g_qlo[o] = lv; }
                            else        { g_khi[o] = hv; g_klo[o] = lv; }
                        }
                    } else {
                        Cout[(size_t)m * DMODEL + n] = v;
                    }
                }
            }
        }
    }
}

// ---------------------------------------------------------------------------
// Tensorized flash attention (fp16) — unchanged from best (R6) kernel.
// QK = Qh*Kh + Qh*Kl + Ql*Kh; PV = Ph*Vh + Pl*Vh (= P*Vh exactly).
// ---------------------------------------------------------------------------
#define AQH_OFF   0
#define AQL_OFF   18432
#define AKH_OFF   36864
#define AKL_OFF   55296
#define AVH_OFF   73728
#define ABIAS_OFF 91136     // AVH + 64*272
#define ATT_SMEM  91648
#define VROWB     272       // 128 keys * 2B + 16B pad

__global__ __launch_bounds__(256) void flash_attn_mma_kernel(const int* __restrict__ mask)
{
    extern __shared__ char smem[];
    const uint32_t sbase = smem_u32(smem);
    const int tid  = threadIdx.x;
    const int wid  = tid >> 5;
    const int lane = tid & 31;
    const int qb   = blockIdx.x;
    const int bh   = blockIdx.y;
    const int b    = bh >> 4;
    const int h    = bh & 15;
    const int q0   = qb * 128;
    const int r0   = wid * 16;
    const int er   = lane >> 2;
    const int ec   = (lane & 3) * 2;

    // load Q hi/lo tile (128 x 64)
    {
        const uint4* Qh4 = (const uint4*)(g_qhi + ((size_t)bh * SEQ + q0) * HDIM);
        const uint4* Ql4 = (const uint4*)(g_qlo + ((size_t)bh * SEQ + q0) * HDIM);
#pragma unroll
        for (int it = 0; it < 4; it++) {
            int e = tid + it * 256;
            int row = e >> 3, seg = e & 7;
            uint32_t soff = (uint32_t)(row * ROWB + seg * 16);
            *(uint4*)(smem + AQH_OFF + soff) = Qh4[row * 8 + seg];
            *(uint4*)(smem + AQL_OFF + soff) = Ql4[row * 8 + seg];
        }
    }

    float m_s[2] = {-1e30f, -1e30f};
    float l_s[2] = {0.f, 0.f};
    float o[8][4];
#pragma unroll
    for (int i = 0; i < 8; i++)
#pragma unroll
        for (int c = 0; c < 4; c++) o[i][c] = 0.f;

    const uint32_t a_base = sbase + (uint32_t)((r0 + (lane & 15)) * ROWB + ((lane >> 4) * 8) * 2);
    const uint32_t b_base = sbase + AKH_OFF +
        (uint32_t)(((lane & 7) + (lane >> 4) * 8) * ROWB + (((lane >> 3) & 1) * 8) * 2);
    const uint32_t v_base = sbase + AVH_OFF +
        (uint32_t)(((lane & 7) + (lane >> 4) * 8) * VROWB + (((lane >> 3) & 1) * 8) * 2);

    for (int kb = 0; kb <= qb; kb++) {
        const int j0 = kb * 128;
        // ---- stage K hi/lo (128 x 64), V hi (64 x 128), mask bias ----
        {
            const uint4* Kh4 = (const uint4*)(g_khi + ((size_t)bh * SEQ + j0) * HDIM);
            const uint4* Kl4 = (const uint4*)(g_klo + ((size_t)bh * SEQ + j0) * HDIM);
#pragma unroll
            for (int it = 0; it < 4; it++) {
                int e = tid + it * 256;
                int row = e >> 3, seg = e & 7;
                uint32_t soff = (uint32_t)(row * ROWB + seg * 16);
                *(uint4*)(smem + AKH_OFF + soff) = Kh4[row * 8 + seg];
                *(uint4*)(smem + AKL_OFF + soff) = Kl4[row * 8 + seg];
            }
#pragma unroll
            for (int it = 0; it < 4; it++) {
                int e = tid + it * 256;
                int d = e >> 4, seg = e & 15;
                uint32_t soff = (uint32_t)(d * VROWB + seg * 16);
                size_t gi = (((size_t)(bh * HDIM + d) * SEQ + j0) >> 3) + seg;
                *(uint4*)(smem + AVH_OFF + soff) = ((const uint4*)g_vhi)[gi];
            }
            if (tid < 128)
                *(float*)(smem + ABIAS_OFF + tid * 4) =
                    (mask[b * SEQ + j0 + tid] == 0) ? NEG_INF_F : 0.f;
        }
        __syncthreads();

        // ---- scores: 16 n-frags x 4 k-steps x 3 terms ----
        float sc[16][4];
#pragma unroll
        for (int i = 0; i < 16; i++)
#pragma unroll
            for (int c = 0; c < 4; c++) sc[i][c] = 0.f;

#pragma unroll
        for (int ks = 0; ks < 4; ks++) {
            uint32_t qh[4], ql[4];
            ldm_x4(qh, a_base + AQH_OFF + ks * 32);
            ldm_x4(ql, a_base + AQL_OFF + ks * 32);
#pragma unroll
            for (int np = 0; np < 8; np++) {
                uint32_t kh[4], kl[4];
                ldm_x4(kh, b_base + ks * 32 + np * 16 * ROWB);
                ldm_x4(kl, b_base + (AKL_OFF - AKH_OFF) + ks * 32 + np * 16 * ROWB);
                mma16816(sc[2 * np],     qh, kh);
                mma16816(sc[2 * np + 1], qh, kh + 2);
                mma16816(sc[2 * np],     qh, kl);
                mma16816(sc[2 * np + 1], qh, kl + 2);
                mma16816(sc[2 * np],     ql, kh);
                mma16816(sc[2 * np + 1], ql, kh + 2);
            }
        }

        // ---- pad-mask bias + causal (diagonal block only) ----
#pragma unroll
        for (int nf = 0; nf < 16; nf++) {
            float2 bv = *(const float2*)(smem + ABIAS_OFF + (nf * 8 + ec) * 4);
            sc[nf][0] += bv.x; sc[nf][1] += bv.y;
            sc[nf][2] += bv.x; sc[nf][3] += bv.y;
        }
        if (kb == qb) {
            int rl0 = r0 + er, rl1 = r0 + er + 8;
#pragma unroll
            for (int nf = 0; nf < 16; nf++) {
                int c0 = nf * 8 + ec, c1 = c0 + 1;
                if (c0 > rl0) sc[nf][0] = NEG_INF_F;
                if (c1 > rl0) sc[nf][1] = NEG_INF_F;
                if (c0 > rl1) sc[nf][2] = NEG_INF_F;
                if (c1 > rl1) sc[nf][3] = NEG_INF_F;
            }
        }

        // ---- online softmax (rows er / er+8; reduce over lane quads) ----
#pragma unroll
        for (int rr = 0; rr < 2; rr++) {
            float bm = -1e30f;
#pragma unroll
            for (int nf = 0; nf < 16; nf++)
                bm = fmaxf(bm, fmaxf(sc[nf][rr * 2], sc[nf][rr * 2 + 1]));
            bm = fmaxf(bm, __shfl_xor_sync(0xffffffffu, bm, 1));
            bm = fmaxf(bm, __shfl_xor_sync(0xffffffffu, bm, 2));
            float m_new = fmaxf(fmaxf(m_s[rr], bm), -1e29f);
            float alpha = __expf(m_s[rr] - m_new);
            float ls = 0.f;
#pragma unroll
            for (int nf = 0; nf < 16; nf++) {
                float p0 = __expf(sc[nf][rr * 2]     - m_new);
                float p1 = __expf(sc[nf][rr * 2 + 1] - m_new);
                sc[nf][rr * 2] = p0; sc[nf][rr * 2 + 1] = p1;
                ls += p0 + p1;
            }
            ls += __shfl_xor_sync(0xffffffffu, ls, 1);
            ls += __shfl_xor_sync(0xffffffffu, ls, 2);
            l_s[rr] = l_s[rr] * alpha + ls;
            m_s[rr] = m_new;
#pragma unroll
            for (int nf = 0; nf < 8; nf++) {
                o[nf][rr * 2] *= alpha; o[nf][rr * 2 + 1] *= alpha;
            }
        }

        // ---- PV: P hi/lo (regs) x Vh(T): P*Vh exactly ----
#pragma unroll
        for (int ks = 0; ks < 8; ks++) {
            uint32_t ah[4], al[4];
            ah[0] = cvt_f16x2(sc[2 * ks][1], sc[2 * ks][0]);
            ah[1] = cvt_f16x2(sc[2 * ks][3], sc[2 * ks][2]);
            ah[2] = cvt_f16x2(sc[2 * ks + 1][1], sc[2 * ks + 1][0]);
            ah[3] = cvt_f16x2(sc[2 * ks + 1][3], sc[2 * ks + 1][2]);
            al[0] = cvt_f16x2(sc[2 * ks][1] - f16x2_hi(ah[0]),
                              sc[2 * ks][0] - f16x2_lo(ah[0]));
            al[1] = cvt_f16x2(sc[2 * ks][3] - f16x2_hi(ah[1]),
                              sc[2 * ks][2] - f16x2_lo(ah[1]));
            al[2] = cvt_f16x2(sc[2 * ks + 1][1] - f16x2_hi(ah[2]),
                              sc[2 * ks + 1][0] - f16x2_lo(ah[2]));
            al[3] = cvt_f16x2(sc[2 * ks + 1][3] - f16x2_hi(ah[3]),
                              sc[2 * ks + 1][2] - f16x2_lo(ah[3]));
#pragma unroll
            for (int np = 0; np < 4; np++) {
                uint32_t vh[4];
                ldm_x4(vh, v_base + ks * 32 + np * 16 * VROWB);
                mma16816(o[2 * np],     ah, vh);
                mma16816(o[2 * np + 1], ah, vh + 2);
                mma16816(o[2 * np],     al, vh);
                mma16816(o[2 * np + 1], al, vh + 2);
            }
        }
        __syncthreads();
    }

    // ---- epilogue: normalize, split to fp16 hi/lo, store (B,S,D) ----
#pragma unroll
    for (int rr = 0; rr < 2; rr++) {
        float inv = 1.f / l_s[rr];
        int row = q0 + r0 + er + rr * 8;
        size_t base = ((size_t)b * SEQ + row) * DMODEL + h * HDIM;
#pragma unroll
        for (int nf = 0; nf < 8; nf++) {
            int d = nf * 8 + ec;
            float v0 = o[nf][rr * 2] * inv;
            float v1 = o[nf][rr * 2 + 1] * inv;
            __half2 hh;
            hh.x = __float2half_rn(v0);
            hh.y = __float2half_rn(v1);
            __half2 ll;
            ll.x = __float2half_rn(v0 - __half2float(hh.x));
            ll.y = __float2half_rn(v1 - __half2float(hh.y));
            *(__half2*)(g_ahi + base + d) = hh;
            *(__half2*)(g_alo + base + d) = ll;
        }
    }
}

// ---------------------------------------------------------------------------
// Entry point
// ---------------------------------------------------------------------------
extern "C" void kernel_launch(void* const* d_in, const int* in_sizes, int n_in,
                              void* d_out, int out_size)
{
    const float* x      = (const float*)d_in[0];   // (4, 2048, 1024) fp32
    const int*   mask   = (const int*)d_in[1];     // (4, 2048) int32
    const float* w_qkv  = (const float*)d_in[2];   // (1024, 3072) fp32
    const float* w_out  = (const float*)d_in[3];   // (1024, 1024) fp32
    float*       out    = (float*)d_out;           // (4, 2048, 1024) fp32

    (void)in_sizes; (void)n_in; (void)out_size;

    cudaFuncSetAttribute(mma_gemm_kernel<0>,
                         cudaFuncAttributeMaxDynamicSharedMemorySize, GEMM_SMEM_BYTES);
    cudaFuncSetAttribute(mma_gemm_kernel<1>,
                         cudaFuncAttributeMaxDynamicSharedMemorySize, GEMM_SMEM_BYTES);
    cudaFuncSetAttribute(flash_attn_mma_kernel,
                         cudaFuncAttributeMaxDynamicSharedMemorySize, ATT_SMEM);

    // prep: fp16 splits
    convert_split_kernel<<<(MROWS * DMODEL / 4 + 255) / 256, 256>>>(x, MROWS * DMODEL / 4);
    transpose_split_kernel<<<dim3(NQKV / 32, DMODEL / 32), dim3(32, 8)>>>(w_qkv, 0, NQKV);
    transpose_split_kernel<<<dim3(DMODEL / 32, DMODEL / 32), dim3(32, 8)>>>(w_out, 1, DMODEL);

    // 1) QKV projection -> q/k hi/lo [bh][s][d], v hi transposed [bh][d][s]
    mma_gemm_kernel<0><<<dim3(NQKV / 256, MROWS / 128), 256, GEMM_SMEM_BYTES>>>(nullptr);

    // 2) Tensorized causal flash attention -> g_ahi/g_alo (B,S,D)
    flash_attn_mma_kernel<<<dim3(SEQ / 128, BATCH * NHEADS), 256, ATT_SMEM>>>(mask);

    // 3) Output projection -> d_out
    mma_gemm_kernel<1><<<dim3(DMODEL / 256, MROWS / 128), 256, GEMM_SMEM_BYTES>>>(out);
}

// round 11
// speedup vs baseline: 1.1246x; 1.1246x over previous
#include <cuda_runtime.h>
#include <cuda_fp16.h>
#include <cstdint>
#include <math.h>

// ---------------------------------------------------------------------------
// Problem constants
// ---------------------------------------------------------------------------
#define BATCH    4
#define SEQ      2048
#define DMODEL   1024
#define NHEADS   16
#define HDIM     64
#define NEG_INF_F (-1e30f)

#define MROWS   (BATCH * SEQ)       // 8192
#define NQKV    (3 * DMODEL)        // 3072

// ---------------------------------------------------------------------------
// Device scratch (fp16 hi/lo splits)
// ---------------------------------------------------------------------------
__device__ __half g_xhi[(size_t)MROWS * DMODEL];
__device__ __half g_xlo[(size_t)MROWS * DMODEL];
__device__ __half g_ahi[(size_t)MROWS * DMODEL];
__device__ __half g_alo[(size_t)MROWS * DMODEL];
// weights, hi only, transposed [N][K]
__device__ __half g_wqh[(size_t)NQKV * DMODEL];
__device__ __half g_woh[(size_t)DMODEL * DMODEL];
// attention operands: Q (pre-scaled 1/8) hi/lo, K hi/lo in [bh][s][d];
// V hi only, transposed [bh][d][s]
__device__ __half g_qhi[(size_t)BATCH * NHEADS * SEQ * HDIM];
__device__ __half g_qlo[(size_t)BATCH * NHEADS * SEQ * HDIM];
__device__ __half g_khi[(size_t)BATCH * NHEADS * SEQ * HDIM];
__device__ __half g_klo[(size_t)BATCH * NHEADS * SEQ * HDIM];
__device__ __half g_vhi[(size_t)BATCH * NHEADS * HDIM * SEQ];

// ---------------------------------------------------------------------------
// Portable PTX helpers (mma.sync / ldmatrix — plain compute_103 OK)
// ---------------------------------------------------------------------------
__device__ __forceinline__ uint32_t smem_u32(const void* p) {
    uint32_t a;
    asm("{ .reg .u64 t; cvta.to.shared.u64 t, %1; cvt.u32.u64 %0, t; }"
        : "=r"(a) : "l"(p));
    return a;
}

__device__ __forceinline__ void ldm_x4(uint32_t* r, uint32_t addr) {
    asm volatile("ldmatrix.sync.aligned.m8n8.x4.shared.b16 {%0,%1,%2,%3}, [%4];"
                 : "=r"(r[0]), "=r"(r[1]), "=r"(r[2]), "=r"(r[3]) : "r"(addr));
}

__device__ __forceinline__ void mma16816(float* d, const uint32_t* a, const uint32_t* b) {
    asm volatile(
        "mma.sync.aligned.m16n8k16.row.col.f32.f16.f16.f32 "
        "{%0,%1,%2,%3}, {%4,%5,%6,%7}, {%8,%9}, {%0,%1,%2,%3};"
        : "+f"(d[0]), "+f"(d[1]), "+f"(d[2]), "+f"(d[3])
        : "r"(a[0]), "r"(a[1]), "r"(a[2]), "r"(a[3]), "r"(b[0]), "r"(b[1]));
}

// pack two fp32 into f16x2: high half = hi_val, low half = lo_val
__device__ __forceinline__ uint32_t cvt_f16x2(float hi_val, float lo_val) {
    uint32_t r;
    asm("cvt.rn.f16x2.f32 %0, %1, %2;" : "=r"(r) : "f"(hi_val), "f"(lo_val));
    return r;
}
__device__ __forceinline__ float f16x2_lo(uint32_t v) {
    __half2 t = *(__half2*)&v; return __half2float(t.x);
}
__device__ __forceinline__ float f16x2_hi(uint32_t v) {
    __half2 t = *(__half2*)&v; return __half2float(t.y);
}

// ---------------------------------------------------------------------------
// Conversion: x fp32 -> (hi, lo) fp16 split
// ---------------------------------------------------------------------------
__global__ __launch_bounds__(256) void convert_split_kernel(
    const float* __restrict__ src, int n4)
{
    int i = blockIdx.x * 256 + threadIdx.x;
    if (i >= n4) return;
    float4 v = ((const float4*)src)[i];
    __half h0 = __float2half_rn(v.x);
    __half h1 = __float2half_rn(v.y);
    __half h2 = __float2half_rn(v.z);
    __half h3 = __float2half_rn(v.w);
    __half2 ph0; ph0.x = h0; ph0.y = h1;
    __half2 ph1; ph1.x = h2; ph1.y = h3;
    __half2 pl0;
    pl0.x = __float2half_rn(v.x - __half2float(h0));
    pl0.y = __float2half_rn(v.y - __half2float(h1));
    __half2 pl1;
    pl1.x = __float2half_rn(v.z - __half2float(h2));
    pl1.y = __float2half_rn(v.w - __half2float(h3));
    ((__half2*)g_xhi)[2 * i]     = ph0;
    ((__half2*)g_xhi)[2 * i + 1] = ph1;
    ((__half2*)g_xlo)[2 * i]     = pl0;
    ((__half2*)g_xlo)[2 * i + 1] = pl1;
}

// W [K x N] fp32 -> transposed [N x K] fp16 hi only
__global__ __launch_bounds__(256) void transpose_split_kernel(
    const float* __restrict__ src, int sel, int N)
{
    __shared__ float tile[32][33];
    const int K = DMODEL;
    __half* hi = (sel == 0) ? g_wqh : g_woh;

    int tx = threadIdx.x;
    int ty = threadIdx.y;
    int n0 = blockIdx.x * 32;
    int k0 = blockIdx.y * 32;

#pragma unroll
    for (int i = 0; i < 4; i++)
        tile[ty + 8 * i][tx] = src[(size_t)(k0 + ty + 8 * i) * N + n0 + tx];
    __syncthreads();
#pragma unroll
    for (int i = 0; i < 4; i++) {
        float v = tile[tx][ty + 8 * i];
        hi[(size_t)(n0 + ty + 8 * i) * K + k0 + tx] = __float2half_rn(v);
    }
}

// ---------------------------------------------------------------------------
// mma.sync GEMM, 2-term fp16: D = (Ah + Al) * Bh  (= A * Bh exactly).
// CTA 128x128, 8 warps 2x4, warp 64x32, K-chunk 64, single-buffered (R6 base).
// Inner loop restructured: ALL fragments loaded up front (ah/al in separate
// registers), then 32 back-to-back MMAs — deep independent chain, no
// mid-batch LDSM/WAR reload.
// MODE 0: epilogue -> q/k hi/lo [bh][s][d], v hi transposed [bh][d][s].
// MODE 1: plain fp32 store into Cout.
// ---------------------------------------------------------------------------
#define ROWB 144
#define TILE_BYTES (128 * ROWB)           // 18432
#define OFF_AL TILE_BYTES
#define OFF_BH (2 * TILE_BYTES)
#define GEMM_SMEM_BYTES (3 * TILE_BYTES)  // 55296

template<int MODE>
__global__ __launch_bounds__(256, 2) void mma_gemm_kernel(float* __restrict__ Cout)
{
    extern __shared__ char smem[];
    const uint32_t sbase = smem_u32(smem);

    const int tid  = threadIdx.x;
    const int wid  = tid >> 5;
    const int lane = tid & 31;
    const int wm   = wid >> 2;
    const int wn   = wid & 3;
    const int m0   = blockIdx.y * 128;
    const int n0   = blockIdx.x * 128;

    const __half* Ahi = (MODE == 0) ? g_xhi : g_ahi;
    const __half* Alo = (MODE == 0) ? g_xlo : g_alo;
    const __half* Bhi = (MODE == 0) ? g_wqh : g_woh;

    const uint4* A4h = (const uint4*)Ahi;   // row stride = 128 uint4
    const uint4* A4l = (const uint4*)Alo;
    const uint4* B4h = (const uint4*)Bhi;

    float acc[4][4][4];
#pragma unroll
    for (int i = 0; i < 4; i++)
#pragma unroll
        for (int j = 0; j < 4; j++)
#pragma unroll
            for (int c = 0; c < 4; c++) acc[i][j][c] = 0.f;

    const int a_row = wm * 64 + (lane & 15);
    const int a_col = (lane >> 4) * 8;
    const int b_row = wn * 32 + (lane & 7) + (lane >> 4) * 8;
    const int b_col = ((lane >> 3) & 1) * 8;

    for (int kc = 0; kc < 16; kc++) {
        // ---- stage 3 tiles: 128 rows x 64 fp16 each ----
#pragma unroll
        for (int it = 0; it < 4; it++) {
            int e   = tid + it * 256;
            int row = e >> 3;
            int seg = e & 7;
            uint32_t soff = (uint32_t)(row * ROWB + seg * 16);
            size_t aidx = (size_t)(m0 + row) * 128 + kc * 8 + seg;
            size_t bidx = (size_t)(n0 + row) * 128 + kc * 8 + seg;
            uint4 vah = A4h[aidx];
            uint4 val = A4l[aidx];
            uint4 vbh = B4h[bidx];
            *(uint4*)(smem + soff)          = vah;
            *(uint4*)(smem + OFF_AL + soff) = val;
            *(uint4*)(smem + OFF_BH + soff) = vbh;
        }
        __syncthreads();

#pragma unroll
        for (int ks = 0; ks < 4; ks++) {
            uint32_t a_addr = sbase + (uint32_t)(a_row * ROWB + (ks * 16 + a_col) * 2);
            uint32_t b_addr = sbase + OFF_BH +
                              (uint32_t)(b_row * ROWB + (ks * 16 + b_col) * 2);

            uint32_t ah[4][4];   // A hi fragments
            uint32_t al[4][4];   // A lo fragments (separate regs — no WAR reload)
            uint32_t bh[4][2];

#pragma unroll
            for (int mi = 0; mi < 4; mi++)
                ldm_x4(ah[mi], a_addr + mi * 16 * ROWB);
#pragma unroll
            for (int mi = 0; mi < 4; mi++)
                ldm_x4(al[mi], a_addr + OFF_AL + mi * 16 * ROWB);
#pragma unroll
            for (int np = 0; np < 2; np++) {
                uint32_t r[4];
                ldm_x4(r, b_addr + np * 16 * ROWB);
                bh[np * 2][0] = r[0]; bh[np * 2][1] = r[1];
                bh[np * 2 + 1][0] = r[2]; bh[np * 2 + 1][1] = r[3];
            }

            // 32 back-to-back MMAs, all operands resident
#pragma unroll
            for (int mi = 0; mi < 4; mi++)
#pragma unroll
                for (int ni = 0; ni < 4; ni++)
                    mma16816(acc[mi][ni], ah[mi], bh[ni]);
#pragma unroll
            for (int mi = 0; mi < 4; mi++)
#pragma unroll
                for (int ni = 0; ni < 4; ni++)
                    mma16816(acc[mi][ni], al[mi], bh[ni]);
        }
        __syncthreads();
    }

    const int er = lane >> 2;
    const int ec = (lane & 3) * 2;
#pragma unroll
    for (int mi = 0; mi < 4; mi++) {
#pragma unroll
        for (int rr = 0; rr < 2; rr++) {
            int m = m0 + wm * 64 + mi * 16 + er + rr * 8;
            int b = m >> 11;
            int s = m & 2047;
#pragma unroll
            for (int ni = 0; ni < 4; ni++) {
#pragma unroll
                for (int cc = 0; cc < 2; cc++) {
                    int n = n0 + wn * 32 + ni * 8 + ec + cc;
                    float v = acc[mi][ni][rr * 2 + cc];
                    if (MODE == 0) {
                        int t = n >> 10;
                        int h = (n >> 6) & 15;
                        int d = n & 63;
                        if (t == 0) v *= 0.125f;   // fold 1/sqrt(hd) into Q
                        __half hv = __float2half_rn(v);
                        int bh_i = b * NHEADS + h;
                        if (t == 2) {
                            g_vhi[((size_t)bh_i * HDIM + d) * SEQ + s] = hv;
                        } else {
                            __half lv = __float2half_rn(v - __half2float(hv));
                            size_t o = ((size_t)bh_i * SEQ + s) * HDIM + d;
                            if (t == 0) { g_qhi[o] = hv; g_qlo[o] = lv; }
                            else        { g_khi[o] = hv; g_klo[o] = lv; }
                        }
                    } else {
                        Cout[(size_t)m * DMODEL + n] = v;
                    }
                }
            }
        }
    }
}

// ---------------------------------------------------------------------------
// Tensorized flash attention (fp16) — math identical to best (R6) kernel.
// QK = Qh*Kh + Qh*Kl + Ql*Kh; PV = Ph*Vh + Pl*Vh (= P*Vh exactly).
// Heavy-first scheduling: grid = (B*H, S/128); qb = 15 - blockIdx.y so the
// heaviest causal CTAs start in wave 1 and light ones pack the tail.
// ---------------------------------------------------------------------------
#define AQH_OFF   0
#define AQL_OFF   18432
#define AKH_OFF   36864
#define AKL_OFF   55296
#define AVH_OFF   73728
#define ABIAS_OFF 91136     // AVH + 64*272
#define ATT_SMEM  91648
#define VROWB     272       // 128 keys * 2B + 16B pad

__global__ __launch_bounds__(256) void flash_attn_mma_kernel(const int* __restrict__ mask)
{
    extern __shared__ char smem[];
    const uint32_t sbase = smem_u32(smem);
    const int tid  = threadIdx.x;
    const int wid  = tid >> 5;
    const int lane = tid & 31;
    const int qb   = (int)gridDim.y - 1 - (int)blockIdx.y;  // heavy-first
    const int bh   = blockIdx.x;
    const int b    = bh >> 4;
    const int h    = bh & 15;
    const int q0   = qb * 128;
    const int r0   = wid * 16;
    const int er   = lane >> 2;
    const int ec   = (lane & 3) * 2;

    // load Q hi/lo tile (128 x 64)
    {
        const uint4* Qh4 = (const uint4*)(g_qhi + ((size_t)bh * SEQ + q0) * HDIM);
        const uint4* Ql4 = (const uint4*)(g_qlo + ((size_t)bh * SEQ + q0) * HDIM);
#pragma unroll
        for (int it = 0; it < 4; it++) {
            int e = tid + it * 256;
            int row = e >> 3, seg = e & 7;
            uint32_t soff = (uint32_t)(row * ROWB + seg * 16);
            *(uint4*)(smem + AQH_OFF + soff) = Qh4[row * 8 + seg];
            *(uint4*)(smem + AQL_OFF + soff) = Ql4[row * 8 + seg];
        }
    }

    float m_s[2] = {-1e30f, -1e30f};
    float l_s[2] = {0.f, 0.f};
    float o[8][4];
#pragma unroll
    for (int i = 0; i < 8; i++)
#pragma unroll
        for (int c = 0; c < 4; c++) o[i][c] = 0.f;

    const uint32_t a_base = sbase + (uint32_t)((r0 + (lane & 15)) * ROWB + ((lane >> 4) * 8) * 2);
    const uint32_t b_base = sbase + AKH_OFF +
        (uint32_t)(((lane & 7) + (lane >> 4) * 8) * ROWB + (((lane >> 3) & 1) * 8) * 2);
    const uint32_t v_base = sbase + AVH_OFF +
        (uint32_t)(((lane & 7) + (lane >> 4) * 8) * VROWB + (((lane >> 3) & 1) * 8) * 2);

    for (int kb = 0; kb <= qb; kb++) {
        const int j0 = kb * 128;
        // ---- stage K hi/lo (128 x 64), V hi (64 x 128), mask bias ----
        {
            const uint4* Kh4 = (const uint4*)(g_khi + ((size_t)bh * SEQ + j0) * HDIM);
            const uint4* Kl4 = (const uint4*)(g_klo + ((size_t)bh * SEQ + j0) * HDIM);
#pragma unroll
            for (int it = 0; it < 4; it++) {
                int e = tid + it * 256;
                int row = e >> 3, seg = e & 7;
                uint32_t soff = (uint32_t)(row * ROWB + seg * 16);
                *(uint4*)(smem + AKH_OFF + soff) = Kh4[row * 8 + seg];
                *(uint4*)(smem + AKL_OFF + soff) = Kl4[row * 8 + seg];
            }
#pragma unroll
            for (int it = 0; it < 4; it++) {
                int e = tid + it * 256;
                int d = e >> 4, seg = e & 15;
                uint32_t soff = (uint32_t)(d * VROWB + seg * 16);
                size_t gi = (((size_t)(bh * HDIM + d) * SEQ + j0) >> 3) + seg;
                *(uint4*)(smem + AVH_OFF + soff) = ((const uint4*)g_vhi)[gi];
            }
            if (tid < 128)
                *(float*)(smem + ABIAS_OFF + tid * 4) =
                    (mask[b * SEQ + j0 + tid] == 0) ? NEG_INF_F : 0.f;
        }
        __syncthreads();

        // ---- scores: 16 n-frags x 4 k-steps x 3 terms ----
        float sc[16][4];
#pragma unroll
        for (int i = 0; i < 16; i++)
#pragma unroll
            for (int c = 0; c < 4; c++) sc[i][c] = 0.f;

#pragma unroll
        for (int ks = 0; ks < 4; ks++) {
            uint32_t qh[4], ql[4];
            ldm_x4(qh, a_base + AQH_OFF + ks * 32);
            ldm_x4(ql, a_base + AQL_OFF + ks * 32);
#pragma unroll
            for (int np = 0; np < 8; np++) {
                uint32_t kh[4], kl[4];
                ldm_x4(kh, b_base + ks * 32 + np * 16 * ROWB);
                ldm_x4(kl, b_base + (AKL_OFF - AKH_OFF) + ks * 32 + np * 16 * ROWB);
                mma16816(sc[2 * np],     qh, kh);
                mma16816(sc[2 * np + 1], qh, kh + 2);
                mma16816(sc[2 * np],     qh, kl);
                mma16816(sc[2 * np + 1], qh, kl + 2);
                mma16816(sc[2 * np],     ql, kh);
                mma16816(sc[2 * np + 1], ql, kh + 2);
            }
        }

        // ---- pad-mask bias + causal (diagonal block only) ----
#pragma unroll
        for (int nf = 0; nf < 16; nf++) {
            float2 bv = *(const float2*)(smem + ABIAS_OFF + (nf * 8 + ec) * 4);
            sc[nf][0] += bv.x; sc[nf][1] += bv.y;
            sc[nf][2] += bv.x; sc[nf][3] += bv.y;
        }
        if (kb == qb) {
            int rl0 = r0 + er, rl1 = r0 + er + 8;
#pragma unroll
            for (int nf = 0; nf < 16; nf++) {
                int c0 = nf * 8 + ec, c1 = c0 + 1;
                if (c0 > rl0) sc[nf][0] = NEG_INF_F;
                if (c1 > rl0) sc[nf][1] = NEG_INF_F;
                if (c0 > rl1) sc[nf][2] = NEG_INF_F;
                if (c1 > rl1) sc[nf][3] = NEG_INF_F;
            }
        }

        // ---- online softmax (rows er / er+8; reduce over lane quads) ----
#pragma unroll
        for (int rr = 0; rr < 2; rr++) {
            float bm = -1e30f;
#pragma unroll
            for (int nf = 0; nf < 16; nf++)
                bm = fmaxf(bm, fmaxf(sc[nf][rr * 2], sc[nf][rr * 2 + 1]));
            bm = fmaxf(bm, __shfl_xor_sync(0xffffffffu, bm, 1));
            bm = fmaxf(bm, __shfl_xor_sync(0xffffffffu, bm, 2));
            float m_new = fmaxf(fmaxf(m_s[rr], bm), -1e29f);
            float alpha = __expf(m_s[rr] - m_new);
            float ls = 0.f;
#pragma unroll
            for (int nf = 0; nf < 16; nf++) {
                float p0 = __expf(sc[nf][rr * 2]     - m_new);
                float p1 = __expf(sc[nf][rr * 2 + 1] - m_new);
                sc[nf][rr * 2] = p0; sc[nf][rr * 2 + 1] = p1;
                ls += p0 + p1;
            }
            ls += __shfl_xor_sync(0xffffffffu, ls, 1);
            ls += __shfl_xor_sync(0xffffffffu, ls, 2);
            l_s[rr] = l_s[rr] * alpha + ls;
            m_s[rr] = m_new;
#pragma unroll
            for (int nf = 0; nf < 8; nf++) {
                o[nf][rr * 2] *= alpha; o[nf][rr * 2 + 1] *= alpha;
            }
        }

        // ---- PV: P hi/lo (regs) x Vh(T): P*Vh exactly ----
#pragma unroll
        for (int ks = 0; ks < 8; ks++) {
            uint32_t ah[4], al[4];
            ah[0] = cvt_f16x2(sc[2 * ks][1], sc[2 * ks][0]);
            ah[1] = cvt_f16x2(sc[2 * ks][3], sc[2 * ks][2]);
            ah[2] = cvt_f16x2(sc[2 * ks + 1][1], sc[2 * ks + 1][0]);
            ah[3] = cvt_f16x2(sc[2 * ks + 1][3], sc[2 * ks + 1][2]);
            al[0] = cvt_f16x2(sc[2 * ks][1] - f16x2_hi(ah[0]),
                              sc[2 * ks][0] - f16x2_lo(ah[0]));
            al[1] = cvt_f16x2(sc[2 * ks][3] - f16x2_hi(ah[1]),
                              sc[2 * ks][2] - f16x2_lo(ah[1]));
            al[2] = cvt_f16x2(sc[2 * ks + 1][1] - f16x2_hi(ah[2]),
                              sc[2 * ks + 1][0] - f16x2_lo(ah[2]));
            al[3] = cvt_f16x2(sc[2 * ks + 1][3] - f16x2_hi(ah[3]),
                              sc[2 * ks + 1][2] - f16x2_lo(ah[3]));
#pragma unroll
            for (int np = 0; np < 4; np++) {
                uint32_t vh[4];
                ldm_x4(vh, v_base + ks * 32 + np * 16 * VROWB);
                mma16816(o[2 * np],     ah, vh);
                mma16816(o[2 * np + 1], ah, vh + 2);
                mma16816(o[2 * np],     al, vh);
                mma16816(o[2 * np + 1], al, vh + 2);
            }
        }
        __syncthreads();
    }

    // ---- epilogue: normalize, split to fp16 hi/lo, store (B,S,D) ----
#pragma unroll
    for (int rr = 0; rr < 2; rr++) {
        float inv = 1.f / l_s[rr];
        int row = q0 + r0 + er + rr * 8;
        size_t base = ((size_t)b * SEQ + row) * DMODEL + h * HDIM;
#pragma unroll
        for (int nf = 0; nf < 8; nf++) {
            int d = nf * 8 + ec;
            float v0 = o[nf][rr * 2] * inv;
            float v1 = o[nf][rr * 2 + 1] * inv;
            __half2 hh;
            hh.x = __float2half_rn(v0);
            hh.y = __float2half_rn(v1);
            __half2 ll;
            ll.x = __float2half_rn(v0 - __half2float(hh.x));
            ll.y = __float2half_rn(v1 - __half2float(hh.y));
            *(__half2*)(g_ahi + base + d) = hh;
            *(__half2*)(g_alo + base + d) = ll;
        }
    }
}

// ---------------------------------------------------------------------------
// Entry point
// ---------------------------------------------------------------------------
extern "C" void kernel_launch(void* const* d_in, const int* in_sizes, int n_in,
                              void* d_out, int out_size)
{
    const float* x      = (const float*)d_in[0];   // (4, 2048, 1024) fp32
    const int*   mask   = (const int*)d_in[1];     // (4, 2048) int32
    const float* w_qkv  = (const float*)d_in[2];   // (1024, 3072) fp32
    const float* w_out  = (const float*)d_in[3];   // (1024, 1024) fp32
    float*       out    = (float*)d_out;           // (4, 2048, 1024) fp32

    (void)in_sizes; (void)n_in; (void)out_size;

    cudaFuncSetAttribute(mma_gemm_kernel<0>,
                         cudaFuncAttributeMaxDynamicSharedMemorySize, GEMM_SMEM_BYTES);
    cudaFuncSetAttribute(mma_gemm_kernel<1>,
                         cudaFuncAttributeMaxDynamicSharedMemorySize, GEMM_SMEM_BYTES);
    cudaFuncSetAttribute(flash_attn_mma_kernel,
                         cudaFuncAttributeMaxDynamicSharedMemorySize, ATT_SMEM);

    // prep: fp16 splits
    convert_split_kernel<<<(MROWS * DMODEL / 4 + 255) / 256, 256>>>(x, MROWS * DMODEL / 4);
    transpose_split_kernel<<<dim3(NQKV / 32, DMODEL / 32), dim3(32, 8)>>>(w_qkv, 0, NQKV);
    transpose_split_kernel<<<dim3(DMODEL / 32, DMODEL / 32), dim3(32, 8)>>>(w_out, 1, DMODEL);

    // 1) QKV projection -> q/k hi/lo [bh][s][d], v hi transposed [bh][d][s]
    mma_gemm_kernel<0><<<dim3(NQKV / 128, MROWS / 128), 256, GEMM_SMEM_BYTES>>>(nullptr);

    // 2) Tensorized causal flash attention (heavy-first) -> g_ahi/g_alo (B,S,D)
    flash_attn_mma_kernel<<<dim3(BATCH * NHEADS, SEQ / 128), 256, ATT_SMEM>>>(mask);

    // 3) Output projection -> d_out
    mma_gemm_kernel<1><<<dim3(DMODEL / 128, MROWS / 128), 256, GEMM_SMEM_BYTES>>>(out);
}

// round 12
// speedup vs baseline: 1.1861x; 1.0548x over previous
#include <cuda_runtime.h>
#include <cuda_fp16.h>
#include <cstdint>
#include <math.h>

// ---------------------------------------------------------------------------
// Problem constants
// ---------------------------------------------------------------------------
#define BATCH    4
#define SEQ      2048
#define DMODEL   1024
#define NHEADS   16
#define HDIM     64
#define NEG_INF_F (-1e30f)

#define MROWS   (BATCH * SEQ)       // 8192
#define NQKV    (3 * DMODEL)        // 3072

// ---------------------------------------------------------------------------
// Device scratch (fp16 hi/lo splits)
// ---------------------------------------------------------------------------
__device__ __half g_xhi[(size_t)MROWS * DMODEL];
__device__ __half g_xlo[(size_t)MROWS * DMODEL];
__device__ __half g_ahi[(size_t)MROWS * DMODEL];
__device__ __half g_alo[(size_t)MROWS * DMODEL];
// weights, hi only, transposed [N][K]
__device__ __half g_wqh[(size_t)NQKV * DMODEL];
__device__ __half g_woh[(size_t)DMODEL * DMODEL];
// attention operands: Q (pre-scaled 1/8) hi/lo, K hi/lo in [bh][s][d];
// V hi only, transposed [bh][d][s]
__device__ __half g_qhi[(size_t)BATCH * NHEADS * SEQ * HDIM];
__device__ __half g_qlo[(size_t)BATCH * NHEADS * SEQ * HDIM];
__device__ __half g_khi[(size_t)BATCH * NHEADS * SEQ * HDIM];
__device__ __half g_klo[(size_t)BATCH * NHEADS * SEQ * HDIM];
__device__ __half g_vhi[(size_t)BATCH * NHEADS * HDIM * SEQ];

// ---------------------------------------------------------------------------
// Portable PTX helpers (mma.sync / ldmatrix — plain compute_103 OK)
// ---------------------------------------------------------------------------
__device__ __forceinline__ uint32_t smem_u32(const void* p) {
    uint32_t a;
    asm("{ .reg .u64 t; cvta.to.shared.u64 t, %1; cvt.u32.u64 %0, t; }"
        : "=r"(a) : "l"(p));
    return a;
}

__device__ __forceinline__ void ldm_x4(uint32_t* r, uint32_t addr) {
    asm volatile("ldmatrix.sync.aligned.m8n8.x4.shared.b16 {%0,%1,%2,%3}, [%4];"
                 : "=r"(r[0]), "=r"(r[1]), "=r"(r[2]), "=r"(r[3]) : "r"(addr));
}

__device__ __forceinline__ void mma16816(float* d, const uint32_t* a, const uint32_t* b) {
    asm volatile(
        "mma.sync.aligned.m16n8k16.row.col.f32.f16.f16.f32 "
        "{%0,%1,%2,%3}, {%4,%5,%6,%7}, {%8,%9}, {%0,%1,%2,%3};"
        : "+f"(d[0]), "+f"(d[1]), "+f"(d[2]), "+f"(d[3])
        : "r"(a[0]), "r"(a[1]), "r"(a[2]), "r"(a[3]), "r"(b[0]), "r"(b[1]));
}

// pack two fp32 into f16x2: high half = hi_val, low half = lo_val
__device__ __forceinline__ uint32_t cvt_f16x2(float hi_val, float lo_val) {
    uint32_t r;
    asm("cvt.rn.f16x2.f32 %0, %1, %2;" : "=r"(r) : "f"(hi_val), "f"(lo_val));
    return r;
}
__device__ __forceinline__ float f16x2_lo(uint32_t v) {
    __half2 t = *(__half2*)&v; return __half2float(t.x);
}
__device__ __forceinline__ float f16x2_hi(uint32_t v) {
    __half2 t = *(__half2*)&v; return __half2float(t.y);
}

// ---------------------------------------------------------------------------
// Conversion: x fp32 -> (hi, lo) fp16 split
// ---------------------------------------------------------------------------
__global__ __launch_bounds__(256) void convert_split_kernel(
    const float* __restrict__ src, int n4)
{
    int i = blockIdx.x * 256 + threadIdx.x;
    if (i >= n4) return;
    float4 v = ((const float4*)src)[i];
    __half h0 = __float2half_rn(v.x);
    __half h1 = __float2half_rn(v.y);
    __half h2 = __float2half_rn(v.z);
    __half h3 = __float2half_rn(v.w);
    __half2 ph0; ph0.x = h0; ph0.y = h1;
    __half2 ph1; ph1.x = h2; ph1.y = h3;
    __half2 pl0;
    pl0.x = __float2half_rn(v.x - __half2float(h0));
    pl0.y = __float2half_rn(v.y - __half2float(h1));
    __half2 pl1;
    pl1.x = __float2half_rn(v.z - __half2float(h2));
    pl1.y = __float2half_rn(v.w - __half2float(h3));
    ((__half2*)g_xhi)[2 * i]     = ph0;
    ((__half2*)g_xhi)[2 * i + 1] = ph1;
    ((__half2*)g_xlo)[2 * i]     = pl0;
    ((__half2*)g_xlo)[2 * i + 1] = pl1;
}

// W [K x N] fp32 -> transposed [N x K] fp16 hi only
__global__ __launch_bounds__(256) void transpose_split_kernel(
    const float* __restrict__ src, int sel, int N)
{
    __shared__ float tile[32][33];
    const int K = DMODEL;
    __half* hi = (sel == 0) ? g_wqh : g_woh;

    int tx = threadIdx.x;
    int ty = threadIdx.y;
    int n0 = blockIdx.x * 32;
    int k0 = blockIdx.y * 32;

#pragma unroll
    for (int i = 0; i < 4; i++)
        tile[ty + 8 * i][tx] = src[(size_t)(k0 + ty + 8 * i) * N + n0 + tx];
    __syncthreads();
#pragma unroll
    for (int i = 0; i < 4; i++) {
        float v = tile[tx][ty + 8 * i];
        hi[(size_t)(n0 + ty + 8 * i) * K + k0 + tx] = __float2half_rn(v);
    }
}

// ---------------------------------------------------------------------------
// mma.sync GEMM, 2-term fp16: D = (Ah + Al) * Bh  (= A * Bh exactly).
// Exact R6 structure (best measured QKV: 319.9us): CTA 128x128, 8 warps 2x4,
// warp 64x32, K-chunk 64, single-buffered, interleaved A-lo reload.
// MODE 0: epilogue -> q/k hi/lo [bh][s][d], v hi transposed [bh][d][s].
// MODE 1: plain fp32 store into Cout.
// ---------------------------------------------------------------------------
#define ROWB 144
#define TILE_BYTES (128 * ROWB)           // 18432
#define OFF_AL TILE_BYTES
#define OFF_BH (2 * TILE_BYTES)
#define GEMM_SMEM_BYTES (3 * TILE_BYTES)  // 55296

template<int MODE>
__global__ __launch_bounds__(256) void mma_gemm_kernel(float* __restrict__ Cout)
{
    extern __shared__ char smem[];
    const uint32_t sbase = smem_u32(smem);

    const int tid  = threadIdx.x;
    const int wid  = tid >> 5;
    const int lane = tid & 31;
    const int wm   = wid >> 2;
    const int wn   = wid & 3;
    const int m0   = blockIdx.y * 128;
    const int n0   = blockIdx.x * 128;

    const __half* Ahi = (MODE == 0) ? g_xhi : g_ahi;
    const __half* Alo = (MODE == 0) ? g_xlo : g_alo;
    const __half* Bhi = (MODE == 0) ? g_wqh : g_woh;

    const uint4* A4h = (const uint4*)Ahi;   // row stride = 128 uint4
    const uint4* A4l = (const uint4*)Alo;
    const uint4* B4h = (const uint4*)Bhi;

    float acc[4][4][4];
#pragma unroll
    for (int i = 0; i < 4; i++)
#pragma unroll
        for (int j = 0; j < 4; j++)
#pragma unroll
            for (int c = 0; c < 4; c++) acc[i][j][c] = 0.f;

    const int a_row = wm * 64 + (lane & 15);
    const int a_col = (lane >> 4) * 8;
    const int b_row = wn * 32 + (lane & 7) + (lane >> 4) * 8;
    const int b_col = ((lane >> 3) & 1) * 8;

    for (int kc = 0; kc < 16; kc++) {
        // ---- stage 3 tiles: 128 rows x 64 fp16 each ----
#pragma unroll
        for (int it = 0; it < 4; it++) {
            int e   = tid + it * 256;
            int row = e >> 3;
            int seg = e & 7;
            uint32_t soff = (uint32_t)(row * ROWB + seg * 16);
            size_t aidx = (size_t)(m0 + row) * 128 + kc * 8 + seg;
            size_t bidx = (size_t)(n0 + row) * 128 + kc * 8 + seg;
            uint4 vah = A4h[aidx];
            uint4 val = A4l[aidx];
            uint4 vbh = B4h[bidx];
            *(uint4*)(smem + soff)          = vah;
            *(uint4*)(smem + OFF_AL + soff) = val;
            *(uint4*)(smem + OFF_BH + soff) = vbh;
        }
        __syncthreads();

#pragma unroll
        for (int ks = 0; ks < 4; ks++) {
            uint32_t a_addr = sbase + (uint32_t)(a_row * ROWB + (ks * 16 + a_col) * 2);
            uint32_t b_addr = sbase + OFF_BH +
                              (uint32_t)(b_row * ROWB + (ks * 16 + b_col) * 2);

            uint32_t af[4][4];
            uint32_t bh[4][2];

#pragma unroll
            for (int mi = 0; mi < 4; mi++)
                ldm_x4(af[mi], a_addr + mi * 16 * ROWB);
#pragma unroll
            for (int np = 0; np < 2; np++) {
                uint32_t r[4];
                ldm_x4(r, b_addr + np * 16 * ROWB);
                bh[np * 2][0] = r[0]; bh[np * 2][1] = r[1];
                bh[np * 2 + 1][0] = r[2]; bh[np * 2 + 1][1] = r[3];
            }

            // Ah * Bh
#pragma unroll
            for (int mi = 0; mi < 4; mi++)
#pragma unroll
                for (int ni = 0; ni < 4; ni++)
                    mma16816(acc[mi][ni], af[mi], bh[ni]);
            // Al * Bh (reload A frags as lo)
#pragma unroll
            for (int mi = 0; mi < 4; mi++)
                ldm_x4(af[mi], a_addr + OFF_AL + mi * 16 * ROWB);
#pragma unroll
            for (int mi = 0; mi < 4; mi++)
#pragma unroll
                for (int ni = 0; ni < 4; ni++)
                    mma16816(acc[mi][ni], af[mi], bh[ni]);
        }
        __syncthreads();
    }

    const int er = lane >> 2;
    const int ec = (lane & 3) * 2;
#pragma unroll
    for (int mi = 0; mi < 4; mi++) {
#pragma unroll
        for (int rr = 0; rr < 2; rr++) {
            int m = m0 + wm * 64 + mi * 16 + er + rr * 8;
            int b = m >> 11;
            int s = m & 2047;
#pragma unroll
            for (int ni = 0; ni < 4; ni++) {
#pragma unroll
                for (int cc = 0; cc < 2; cc++) {
                    int n = n0 + wn * 32 + ni * 8 + ec + cc;
                    float v = acc[mi][ni][rr * 2 + cc];
                    if (MODE == 0) {
                        int t = n >> 10;
                        int h = (n >> 6) & 15;
                        int d = n & 63;
                        if (t == 0) v *= 0.125f;   // fold 1/sqrt(hd) into Q
                        __half hv = __float2half_rn(v);
                        int bh_i = b * NHEADS + h;
                        if (t == 2) {
                            g_vhi[((size_t)bh_i * HDIM + d) * SEQ + s] = hv;
                        } else {
                            __half lv = __float2half_rn(v - __half2float(hv));
                            size_t o = ((size_t)bh_i * SEQ + s) * HDIM + d;
                            if (t == 0) { g_qhi[o] = hv; g_qlo[o] = lv; }
                            else        { g_khi[o] = hv; g_klo[o] = lv; }
                        }
                    } else {
                        Cout[(size_t)m * DMODEL + n] = v;
                    }
                }
            }
        }
    }
}

// ---------------------------------------------------------------------------
// Tensorized flash attention (fp16), 64-key tiles for 2 CTAs/SM.
// QK = Qh*Kh + Qh*Kl + Ql*Kh; PV = Ph*Vh + Pl*Vh (= P*Vh exactly).
// grid = (B*H, S/128) heavy-first (qb = gridDim.y-1-blockIdx.y).
// 8 warps x 16 query rows; sc[8][4] (32 regs) -> fits 2 CTAs/SM at <=128 regs.
// SMEM/CTA = 64768 B -> 2 CTAs = 129.5 KB.
// ---------------------------------------------------------------------------
#define AQH_OFF   0
#define AQL_OFF   18432
#define AKH_OFF   36864     // K tiles now 64 rows x 144B = 9216 each
#define AKL_OFF   46080
#define AVH_OFF   55296     // V tile 64 d-rows x 144B = 9216
#define ABIAS_OFF 64512     // 64 floats
#define ATT_SMEM  64768
#define VROWB     144       // 64 keys * 2B + 16B pad

__global__ __launch_bounds__(256, 2) void flash_attn_mma_kernel(const int* __restrict__ mask)
{
    extern __shared__ char smem[];
    const uint32_t sbase = smem_u32(smem);
    const int tid  = threadIdx.x;
    const int wid  = tid >> 5;
    const int lane = tid & 31;
    const int qb   = (int)gridDim.y - 1 - (int)blockIdx.y;  // heavy-first
    const int bh   = blockIdx.x;
    const int b    = bh >> 4;
    const int h    = bh & 15;
    const int q0   = qb * 128;
    const int r0   = wid * 16;
    const int er   = lane >> 2;
    const int ec   = (lane & 3) * 2;

    // load Q hi/lo tile (128 x 64)
    {
        const uint4* Qh4 = (const uint4*)(g_qhi + ((size_t)bh * SEQ + q0) * HDIM);
        const uint4* Ql4 = (const uint4*)(g_qlo + ((size_t)bh * SEQ + q0) * HDIM);
#pragma unroll
        for (int it = 0; it < 4; it++) {
            int e = tid + it * 256;
            int row = e >> 3, seg = e & 7;
            uint32_t soff = (uint32_t)(row * ROWB + seg * 16);
            *(uint4*)(smem + AQH_OFF + soff) = Qh4[row * 8 + seg];
            *(uint4*)(smem + AQL_OFF + soff) = Ql4[row * 8 + seg];
        }
    }

    float m_s[2] = {-1e30f, -1e30f};
    float l_s[2] = {0.f, 0.f};
    float o[8][4];
#pragma unroll
    for (int i = 0; i < 8; i++)
#pragma unroll
        for (int c = 0; c < 4; c++) o[i][c] = 0.f;

    const uint32_t a_base = sbase + (uint32_t)((r0 + (lane & 15)) * ROWB + ((lane >> 4) * 8) * 2);
    const uint32_t b_base = sbase + AKH_OFF +
        (uint32_t)(((lane & 7) + (lane >> 4) * 8) * ROWB + (((lane >> 3) & 1) * 8) * 2);
    const uint32_t v_base = sbase + AVH_OFF +
        (uint32_t)(((lane & 7) + (lane >> 4) * 8) * VROWB + (((lane >> 3) & 1) * 8) * 2);

    const int nkb = 2 * qb + 2;          // 64-key blocks up to (qb+1)*128
    for (int kb = 0; kb < nkb; kb++) {
        const int j0 = kb * 64;
        // ---- stage K hi/lo (64 x 64), V hi (64 d x 64 keys), mask bias ----
        {
            const uint4* Kh4 = (const uint4*)(g_khi + ((size_t)bh * SEQ + j0) * HDIM);
            const uint4* Kl4 = (const uint4*)(g_klo + ((size_t)bh * SEQ + j0) * HDIM);
#pragma unroll
            for (int it = 0; it < 2; it++) {
                int e = tid + it * 256;       // 0..511
                int row = e >> 3, seg = e & 7;
                uint32_t soff = (uint32_t)(row * ROWB + seg * 16);
                *(uint4*)(smem + AKH_OFF + soff) = Kh4[row * 8 + seg];
                *(uint4*)(smem + AKL_OFF + soff) = Kl4[row * 8 + seg];
            }
#pragma unroll
            for (int it = 0; it < 2; it++) {
                int e = tid + it * 256;       // 0..511
                int d = e >> 3, seg = e & 7;  // 64 d-rows, 8 segs of 8 keys
                uint32_t soff = (uint32_t)(d * VROWB + seg * 16);
                size_t gi = (((size_t)(bh * HDIM + d) * SEQ + j0) >> 3) + seg;
                *(uint4*)(smem + AVH_OFF + soff) = ((const uint4*)g_vhi)[gi];
            }
            if (tid < 64)
                *(float*)(smem + ABIAS_OFF + tid * 4) =
                    (mask[b * SEQ + j0 + tid] == 0) ? NEG_INF_F : 0.f;
        }
        __syncthreads();

        // ---- scores: 8 n-frags x 4 k-steps x 3 terms ----
        float sc[8][4];
#pragma unroll
        for (int i = 0; i < 8; i++)
#pragma unroll
            for (int c = 0; c < 4; c++) sc[i][c] = 0.f;

#pragma unroll
        for (int ks = 0; ks < 4; ks++) {
            uint32_t qh[4], ql[4];
            ldm_x4(qh, a_base + AQH_OFF + ks * 32);
            ldm_x4(ql, a_base + AQL_OFF + ks * 32);
#pragma unroll
            for (int np = 0; np < 4; np++) {
                uint32_t kh[4], kl[4];
                ldm_x4(kh, b_base + ks * 32 + np * 16 * ROWB);
                ldm_x4(kl, b_base + (AKL_OFF - AKH_OFF) + ks * 32 + np * 16 * ROWB);
                mma16816(sc[2 * np],     qh, kh);
                mma16816(sc[2 * np + 1], qh, kh + 2);
                mma16816(sc[2 * np],     qh, kl);
                mma16816(sc[2 * np + 1], qh, kl + 2);
                mma16816(sc[2 * np],     ql, kh);
                mma16816(sc[2 * np + 1], ql, kh + 2);
            }
        }

        // ---- pad-mask bias + causal (near-diagonal blocks only) ----
#pragma unroll
        for (int nf = 0; nf < 8; nf++) {
            float2 bv = *(const float2*)(smem + ABIAS_OFF + (nf * 8 + ec) * 4);
            sc[nf][0] += bv.x; sc[nf][1] += bv.y;
            sc[nf][2] += bv.x; sc[nf][3] += bv.y;
        }
        if (kb >= 2 * qb) {                    // block may cross the diagonal
            int rl0 = q0 + r0 + er, rl1 = rl0 + 8;
#pragma unroll
            for (int nf = 0; nf < 8; nf++) {
                int c0 = j0 + nf * 8 + ec, c1 = c0 + 1;
                if (c0 > rl0) sc[nf][0] = NEG_INF_F;
                if (c1 > rl0) sc[nf][1] = NEG_INF_F;
                if (c0 > rl1) sc[nf][2] = NEG_INF_F;
                if (c1 > rl1) sc[nf][3] = NEG_INF_F;
            }
        }

        // ---- online softmax (rows er / er+8; reduce over lane quads) ----
#pragma unroll
        for (int rr = 0; rr < 2; rr++) {
            float bm = -1e30f;
#pragma unroll
            for (int nf = 0; nf < 8; nf++)
                bm = fmaxf(bm, fmaxf(sc[nf][rr * 2], sc[nf][rr * 2 + 1]));
            bm = fmaxf(bm, __shfl_xor_sync(0xffffffffu, bm, 1));
            bm = fmaxf(bm, __shfl_xor_sync(0xffffffffu, bm, 2));
            float m_new = fmaxf(fmaxf(m_s[rr], bm), -1e29f);
            float alpha = __expf(m_s[rr] - m_new);
            float ls = 0.f;
#pragma unroll
            for (int nf = 0; nf < 8; nf++) {
                float p0 = __expf(sc[nf][rr * 2]     - m_new);
                float p1 = __expf(sc[nf][rr * 2 + 1] - m_new);
                sc[nf][rr * 2] = p0; sc[nf][rr * 2 + 1] = p1;
                ls += p0 + p1;
            }
            ls += __shfl_xor_sync(0xffffffffu, ls, 1);
            ls += __shfl_xor_sync(0xffffffffu, ls, 2);
            l_s[rr] = l_s[rr] * alpha + ls;
            m_s[rr] = m_new;
#pragma unroll
            for (int nf = 0; nf < 8; nf++) {
                o[nf][rr * 2] *= alpha; o[nf][rr * 2 + 1] *= alpha;
            }
        }

        // ---- PV: P hi/lo (regs) x Vh(T): P*Vh exactly ----
#pragma unroll
        for (int ks = 0; ks < 4; ks++) {
            uint32_t ah[4], al[4];
            ah[0] = cvt_f16x2(sc[2 * ks][1], sc[2 * ks][0]);
            ah[1] = cvt_f16x2(sc[2 * ks][3], sc[2 * ks][2]);
            ah[2] = cvt_f16x2(sc[2 * ks + 1][1], sc[2 * ks + 1][0]);
            ah[3] = cvt_f16x2(sc[2 * ks + 1][3], sc[2 * ks + 1][2]);
            al[0] = cvt_f16x2(sc[2 * ks][1] - f16x2_hi(ah[0]),
                              sc[2 * ks][0] - f16x2_lo(ah[0]));
            al[1] = cvt_f16x2(sc[2 * ks][3] - f16x2_hi(ah[1]),
                              sc[2 * ks][2] - f16x2_lo(ah[1]));
            al[2] = cvt_f16x2(sc[2 * ks + 1][1] - f16x2_hi(ah[2]),
                              sc[2 * ks + 1][0] - f16x2_lo(ah[2]));
            al[3] = cvt_f16x2(sc[2 * ks + 1][3] - f16x2_hi(ah[3]),
                              sc[2 * ks + 1][2] - f16x2_lo(ah[3]));
#pragma unroll
            for (int np = 0; np < 4; np++) {
                uint32_t vh[4];
                ldm_x4(vh, v_base + ks * 32 + np * 16 * VROWB);
                mma16816(o[2 * np],     ah, vh);
                mma16816(o[2 * np + 1], ah, vh + 2);
                mma16816(o[2 * np],     al, vh);
                mma16816(o[2 * np + 1], al, vh + 2);
            }
        }
        __syncthreads();
    }

    // ---- epilogue: normalize, split to fp16 hi/lo, store (B,S,D) ----
#pragma unroll
    for (int rr = 0; rr < 2; rr++) {
        float inv = 1.f / l_s[rr];
        int row = q0 + r0 + er + rr * 8;
        size_t base = ((size_t)b * SEQ + row) * DMODEL + h * HDIM;
#pragma unroll
        for (int nf = 0; nf < 8; nf++) {
            int d = nf * 8 + ec;
            float v0 = o[nf][rr * 2] * inv;
            float v1 = o[nf][rr * 2 + 1] * inv;
            __half2 hh;
            hh.x = __float2half_rn(v0);
            hh.y = __float2half_rn(v1);
            __half2 ll;
            ll.x = __float2half_rn(v0 - __half2float(hh.x));
            ll.y = __float2half_rn(v1 - __half2float(hh.y));
            *(__half2*)(g_ahi + base + d) = hh;
            *(__half2*)(g_alo + base + d) = ll;
        }
    }
}

// ---------------------------------------------------------------------------
// Entry point
// ---------------------------------------------------------------------------
extern "C" void kernel_launch(void* const* d_in, const int* in_sizes, int n_in,
                              void* d_out, int out_size)
{
    const float* x      = (const float*)d_in[0];   // (4, 2048, 1024) fp32
    const int*   mask   = (const int*)d_in[1];     // (4, 2048) int32
    const float* w_qkv  = (const float*)d_in[2];   // (1024, 3072) fp32
    const float* w_out  = (const float*)d_in[3];   // (1024, 1024) fp32
    float*       out    = (float*)d_out;           // (4, 2048, 1024) fp32

    (void)in_sizes; (void)n_in; (void)out_size;

    cudaFuncSetAttribute(mma_gemm_kernel<0>,
                         cudaFuncAttributeMaxDynamicSharedMemorySize, GEMM_SMEM_BYTES);
    cudaFuncSetAttribute(mma_gemm_kernel<1>,
                         cudaFuncAttributeMaxDynamicSharedMemorySize, GEMM_SMEM_BYTES);
    cudaFuncSetAttribute(flash_attn_mma_kernel,
                         cudaFuncAttributeMaxDynamicSharedMemorySize, ATT_SMEM);

    // prep: fp16 splits
    convert_split_kernel<<<(MROWS * DMODEL / 4 + 255) / 256, 256>>>(x, MROWS * DMODEL / 4);
    transpose_split_kernel<<<dim3(NQKV / 32, DMODEL / 32), dim3(32, 8)>>>(w_qkv, 0, NQKV);
    transpose_split_kernel<<<dim3(DMODEL / 32, DMODEL / 32), dim3(32, 8)>>>(w_out, 1, DMODEL);

    // 1) QKV projection -> q/k hi/lo [bh][s][d], v hi transposed [bh][d][s]
    mma_gemm_kernel<0><<<dim3(NQKV / 128, MROWS / 128), 256, GEMM_SMEM_BYTES>>>(nullptr);

    // 2) Tensorized causal flash attention (heavy-first, 2 CTA/SM) -> g_ahi/g_alo
    flash_attn_mma_kernel<<<dim3(BATCH * NHEADS, SEQ / 128), 256, ATT_SMEM>>>(mask);

    // 3) Output projection -> d_out
    mma_gemm_kernel<1><<<dim3(DMODEL / 128, MROWS / 128), 256, GEMM_SMEM_BYTES>>>(out);
}

// round 14
// speedup vs baseline: 1.1925x; 1.0053x over previous
#include <cuda_runtime.h>
#include <cuda_fp16.h>
#include <cstdint>
#include <math.h>

// ---------------------------------------------------------------------------
// Problem constants
// ---------------------------------------------------------------------------
#define BATCH    4
#define SEQ      2048
#define DMODEL   1024
#define NHEADS   16
#define HDIM     64
#define NEG_INF_F (-1e30f)

#define MROWS   (BATCH * SEQ)       // 8192
#define NQKV    (3 * DMODEL)        // 3072

// ---------------------------------------------------------------------------
// Device scratch (fp16 hi/lo splits)
// ---------------------------------------------------------------------------
__device__ __half g_ahi[(size_t)MROWS * DMODEL];
__device__ __half g_alo[(size_t)MROWS * DMODEL];
// weights, hi only, transposed [N][K]
__device__ __half g_wqh[(size_t)NQKV * DMODEL];
__device__ __half g_woh[(size_t)DMODEL * DMODEL];
// attention operands: Q (pre-scaled 1/8) hi/lo, K hi/lo in [bh][s][d];
// V hi only, transposed [bh][d][s]
__device__ __half g_qhi[(size_t)BATCH * NHEADS * SEQ * HDIM];
__device__ __half g_qlo[(size_t)BATCH * NHEADS * SEQ * HDIM];
__device__ __half g_khi[(size_t)BATCH * NHEADS * SEQ * HDIM];
__device__ __half g_klo[(size_t)BATCH * NHEADS * SEQ * HDIM];
__device__ __half g_vhi[(size_t)BATCH * NHEADS * HDIM * SEQ];

// ---------------------------------------------------------------------------
// Portable PTX helpers (mma.sync / ldmatrix — plain compute_103 OK)
// ---------------------------------------------------------------------------
__device__ __forceinline__ uint32_t smem_u32(const void* p) {
    uint32_t a;
    asm("{ .reg .u64 t; cvta.to.shared.u64 t, %1; cvt.u32.u64 %0, t; }"
        : "=r"(a) : "l"(p));
    return a;
}

__device__ __forceinline__ void ldm_x4(uint32_t* r, uint32_t addr) {
    asm volatile("ldmatrix.sync.aligned.m8n8.x4.shared.b16 {%0,%1,%2,%3}, [%4];"
                 : "=r"(r[0]), "=r"(r[1]), "=r"(r[2]), "=r"(r[3]) : "r"(addr));
}

__device__ __forceinline__ void mma16816(float* d, const uint32_t* a, const uint32_t* b) {
    asm volatile(
        "mma.sync.aligned.m16n8k16.row.col.f32.f16.f16.f32 "
        "{%0,%1,%2,%3}, {%4,%5,%6,%7}, {%8,%9}, {%0,%1,%2,%3};"
        : "+f"(d[0]), "+f"(d[1]), "+f"(d[2]), "+f"(d[3])
        : "r"(a[0]), "r"(a[1]), "r"(a[2]), "r"(a[3]), "r"(b[0]), "r"(b[1]));
}

// pack two fp32 into f16x2: high half = hi_val, low half = lo_val
__device__ __forceinline__ uint32_t cvt_f16x2(float hi_val, float lo_val) {
    uint32_t r;
    asm("cvt.rn.f16x2.f32 %0, %1, %2;" : "=r"(r) : "f"(hi_val), "f"(lo_val));
    return r;
}
__device__ __forceinline__ float f16x2_lo(uint32_t v) {
    __half2 t = *(__half2*)&v; return __half2float(t.x);
}
__device__ __forceinline__ float f16x2_hi(uint32_t v) {
    __half2 t = *(__half2*)&v; return __half2float(t.y);
}

// split 8 fp32 (two float4) into hi/lo fp16 uint4s — same math/order as the
// old convert_split_kernel, so SMEM contents (and rel_err) are bit-identical.
__device__ __forceinline__ void split8(float4 v0, float4 v1, uint4& hh, uint4& ll) {
    __half2 h0 = __floats2half2_rn(v0.x, v0.y);
    __half2 h1 = __floats2half2_rn(v0.z, v0.w);
    __half2 h2 = __floats2half2_rn(v1.x, v1.y);
    __half2 h3 = __floats2half2_rn(v1.z, v1.w);
    __half2 l0 = __floats2half2_rn(v0.x - __half2float(h0.x), v0.y - __half2float(h0.y));
    __half2 l1 = __floats2half2_rn(v0.z - __half2float(h1.x), v0.w - __half2float(h1.y));
    __half2 l2 = __floats2half2_rn(v1.x - __half2float(h2.x), v1.y - __half2float(h2.y));
    __half2 l3 = __floats2half2_rn(v1.z - __half2float(h3.x), v1.w - __half2float(h3.y));
    hh.x = *(uint32_t*)&h0; hh.y = *(uint32_t*)&h1;
    hh.z = *(uint32_t*)&h2; hh.w = *(uint32_t*)&h3;
    ll.x = *(uint32_t*)&l0; ll.y = *(uint32_t*)&l1;
    ll.z = *(uint32_t*)&l2; ll.w = *(uint32_t*)&l3;
}

// ---------------------------------------------------------------------------
// W [K x N] fp32 -> transposed [N x K] fp16 hi only
// ---------------------------------------------------------------------------
__global__ __launch_bounds__(256) void transpose_split_kernel(
    const float* __restrict__ src, int sel, int N)
{
    __shared__ float tile[32][33];
    const int K = DMODEL;
    __half* hi = (sel == 0) ? g_wqh : g_woh;

    int tx = threadIdx.x;
    int ty = threadIdx.y;
    int n0 = blockIdx.x * 32;
    int k0 = blockIdx.y * 32;

#pragma unroll
    for (int i = 0; i < 4; i++)
        tile[ty + 8 * i][tx] = src[(size_t)(k0 + ty + 8 * i) * N + n0 + tx];
    __syncthreads();
#pragma unroll
    for (int i = 0; i < 4; i++) {
        float v = tile[tx][ty + 8 * i];
        hi[(size_t)(n0 + ty + 8 * i) * K + k0 + tx] = __float2half_rn(v);
    }
}

// ---------------------------------------------------------------------------
// mma.sync GEMM, 2-term fp16: D = (Ah + Al) * Bh  (= A * Bh exactly).
// R6 structure (best measured): CTA 128x128, 8 warps 2x4, warp 64x32,
// K-chunk 64, single-buffered, interleaved A-lo reload.
// MODE 0: A staged from fp32 X with FUSED hi/lo split (no convert kernel);
//         epilogue -> q/k hi/lo [bh][s][d], v hi transposed [bh][d][s].
// MODE 1: A staged from g_ahi/g_alo fp16; plain fp32 store into Cout.
// ---------------------------------------------------------------------------
#define ROWB 144
#define TILE_BYTES (128 * ROWB)           // 18432
#define OFF_AL TILE_BYTES
#define OFF_BH (2 * TILE_BYTES)
#define GEMM_SMEM_BYTES (3 * TILE_BYTES)  // 55296

template<int MODE>
__global__ __launch_bounds__(256) void mma_gemm_kernel(
    const float* __restrict__ X, float* __restrict__ Cout)
{
    extern __shared__ char smem[];
    const uint32_t sbase = smem_u32(smem);

    const int tid  = threadIdx.x;
    const int wid  = tid >> 5;
    const int lane = tid & 31;
    const int wm   = wid >> 2;
    const int wn   = wid & 3;
    const int m0   = blockIdx.y * 128;
    const int n0   = blockIdx.x * 128;

    const __half* Bhi = (MODE == 0) ? g_wqh : g_woh;
    const uint4* B4h = (const uint4*)Bhi;            // row stride = 128 uint4
    const float4* X4 = (const float4*)X;             // row stride = 256 float4
    const uint4* A4h = (const uint4*)g_ahi;          // MODE 1 path
    const uint4* A4l = (const uint4*)g_alo;

    float acc[4][4][4];
#pragma unroll
    for (int i = 0; i < 4; i++)
#pragma unroll
        for (int j = 0; j < 4; j++)
#pragma unroll
            for (int c = 0; c < 4; c++) acc[i][j][c] = 0.f;

    const int a_row = wm * 64 + (lane & 15);
    const int a_col = (lane >> 4) * 8;
    const int b_row = wn * 32 + (lane & 7) + (lane >> 4) * 8;
    const int b_col = ((lane >> 3) & 1) * 8;

    for (int kc = 0; kc < 16; kc++) {
        // ---- stage 3 tiles: 128 rows x 64 fp16 each ----
#pragma unroll
        for (int it = 0; it < 4; it++) {
            int e   = tid + it * 256;
            int row = e >> 3;
            int seg = e & 7;
            uint32_t soff = (uint32_t)(row * ROWB + seg * 16);
            size_t bidx = (size_t)(n0 + row) * 128 + kc * 8 + seg;
            if (MODE == 0) {
                // fused fp32 -> hi/lo split during staging
                size_t xidx = (size_t)(m0 + row) * 256 + kc * 16 + seg * 2;
                float4 v0 = X4[xidx];
                float4 v1 = X4[xidx + 1];
                uint4 vbh = B4h[bidx];
                uint4 hh, ll;
                split8(v0, v1, hh, ll);
                *(uint4*)(smem + soff)          = hh;
                *(uint4*)(smem + OFF_AL + soff) = ll;
                *(uint4*)(smem + OFF_BH + soff) = vbh;
            } else {
                size_t aidx = (size_t)(m0 + row) * 128 + kc * 8 + seg;
                uint4 vah = A4h[aidx];
                uint4 val = A4l[aidx];
                uint4 vbh = B4h[bidx];
                *(uint4*)(smem + soff)          = vah;
                *(uint4*)(smem + OFF_AL + soff) = val;
                *(uint4*)(smem + OFF_BH + soff) = vbh;
            }
        }
        __syncthreads();

#pragma unroll
        for (int ks = 0; ks < 4; ks++) {
            uint32_t a_addr = sbase + (uint32_t)(a_row * ROWB + (ks * 16 + a_col) * 2);
            uint32_t b_addr = sbase + OFF_BH +
                              (uint32_t)(b_row * ROWB + (ks * 16 + b_col) * 2);

            uint32_t af[4][4];
            uint32_t bh[4][2];

#pragma unroll
            for (int mi = 0; mi < 4; mi++)
                ldm_x4(af[mi], a_addr + mi * 16 * ROWB);
#pragma unroll
            for (int np = 0; np < 2; np++) {
                uint32_t r[4];
                ldm_x4(r, b_addr + np * 16 * ROWB);
                bh[np * 2][0] = r[0]; bh[np * 2][1] = r[1];
                bh[np * 2 + 1][0] = r[2]; bh[np * 2 + 1][1] = r[3];
            }

            // Ah * Bh
#pragma unroll
            for (int mi = 0; mi < 4; mi++)
#pragma unroll
                for (int ni = 0; ni < 4; ni++)
                    mma16816(acc[mi][ni], af[mi], bh[ni]);
            // Al * Bh (reload A frags as lo)
#pragma unroll
            for (int mi = 0; mi < 4; mi++)
                ldm_x4(af[mi], a_addr + OFF_AL + mi * 16 * ROWB);
#pragma unroll
            for (int mi = 0; mi < 4; mi++)
#pragma unroll
                for (int ni = 0; ni < 4; ni++)
                    mma16816(acc[mi][ni], af[mi], bh[ni]);
        }
        __syncthreads();
    }

    const int er = lane >> 2;
    const int ec = (lane & 3) * 2;
#pragma unroll
    for (int mi = 0; mi < 4; mi++) {
#pragma unroll
        for (int rr = 0; rr < 2; rr++) {
            int m = m0 + wm * 64 + mi * 16 + er + rr * 8;
            int b = m >> 11;
            int s = m & 2047;
#pragma unroll
            for (int ni = 0; ni < 4; ni++) {
#pragma unroll
                for (int cc = 0; cc < 2; cc++) {
                    int n = n0 + wn * 32 + ni * 8 + ec + cc;
                    float v = acc[mi][ni][rr * 2 + cc];
                    if (MODE == 0) {
                        int t = n >> 10;
                        int h = (n >> 6) & 15;
                        int d = n & 63;
                        if (t == 0) v *= 0.125f;   // fold 1/sqrt(hd) into Q
                        __half hv = __float2half_rn(v);
                        int bh_i = b * NHEADS + h;
                        if (t == 2) {
                            g_vhi[((size_t)bh_i * HDIM + d) * SEQ + s] = hv;
                        } else {
                            __half lv = __float2half_rn(v - __half2float(hv));
                            size_t o = ((size_t)bh_i * SEQ + s) * HDIM + d;
                            if (t == 0) { g_qhi[o] = hv; g_qlo[o] = lv; }
                            else        { g_khi[o] = hv; g_klo[o] = lv; }
                        }
                    } else {
                        Cout[(size_t)m * DMODEL + n] = v;
                    }
                }
            }
        }
    }
}

// ---------------------------------------------------------------------------
// Tensorized flash attention (fp16), 64-key tiles, 2 CTAs/SM, heavy-first.
// QK = Qh*Kh + Qh*Kl + Ql*Kh; PV = Ph*Vh + Pl*Vh (= P*Vh exactly).
// Unchanged from passing R11 kernel.
// ---------------------------------------------------------------------------
#define AQH_OFF   0
#define AQL_OFF   18432
#define AKH_OFF   36864     // K tiles 64 rows x 144B = 9216 each
#define AKL_OFF   46080
#define AVH_OFF   55296     // V tile 64 d-rows x 144B = 9216
#define ABIAS_OFF 64512     // 64 floats
#define ATT_SMEM  64768
#define VROWB     144       // 64 keys * 2B + 16B pad

__global__ __launch_bounds__(256, 2) void flash_attn_mma_kernel(const int* __restrict__ mask)
{
    extern __shared__ char smem[];
    const uint32_t sbase = smem_u32(smem);
    const int tid  = threadIdx.x;
    const int wid  = tid >> 5;
    const int lane = tid & 31;
    const int qb   = (int)gridDim.y - 1 - (int)blockIdx.y;  // heavy-first
    const int bh   = blockIdx.x;
    const int b    = bh >> 4;
    const int h    = bh & 15;
    const int q0   = qb * 128;
    const int r0   = wid * 16;
    const int er   = lane >> 2;
    const int ec   = (lane & 3) * 2;

    // load Q hi/lo tile (128 x 64)
    {
        const uint4* Qh4 = (const uint4*)(g_qhi + ((size_t)bh * SEQ + q0) * HDIM);
        const uint4* Ql4 = (const uint4*)(g_qlo + ((size_t)bh * SEQ + q0) * HDIM);
#pragma unroll
        for (int it = 0; it < 4; it++) {
            int e = tid + it * 256;
            int row = e >> 3, seg = e & 7;
            uint32_t soff = (uint32_t)(row * ROWB + seg * 16);
            *(uint4*)(smem + AQH_OFF + soff) = Qh4[row * 8 + seg];
            *(uint4*)(smem + AQL_OFF + soff) = Ql4[row * 8 + seg];
        }
    }

    float m_s[2] = {-1e30f, -1e30f};
    float l_s[2] = {0.f, 0.f};
    float o[8][4];
#pragma unroll
    for (int i = 0; i < 8; i++)
#pragma unroll
        for (int c = 0; c < 4; c++) o[i][c] = 0.f;

    const uint32_t a_base = sbase + (uint32_t)((r0 + (lane & 15)) * ROWB + ((lane >> 4) * 8) * 2);
    const uint32_t b_base = sbase + AKH_OFF +
        (uint32_t)(((lane & 7) + (lane >> 4) * 8) * ROWB + (((lane >> 3) & 1) * 8) * 2);
    const uint32_t v_base = sbase + AVH_OFF +
        (uint32_t)(((lane & 7) + (lane >> 4) * 8) * VROWB + (((lane >> 3) & 1) * 8) * 2);

    const int nkb = 2 * qb + 2;          // 64-key blocks up to (qb+1)*128
    for (int kb = 0; kb < nkb; kb++) {
        const int j0 = kb * 64;
        // ---- stage K hi/lo (64 x 64), V hi (64 d x 64 keys), mask bias ----
        {
            const uint4* Kh4 = (const uint4*)(g_khi + ((size_t)bh * SEQ + j0) * HDIM);
            const uint4* Kl4 = (const uint4*)(g_klo + ((size_t)bh * SEQ + j0) * HDIM);
#pragma unroll
            for (int it = 0; it < 2; it++) {
                int e = tid + it * 256;       // 0..511
                int row = e >> 3, seg = e & 7;
                uint32_t soff = (uint32_t)(row * ROWB + seg * 16);
                *(uint4*)(smem + AKH_OFF + soff) = Kh4[row * 8 + seg];
                *(uint4*)(smem + AKL_OFF + soff) = Kl4[row * 8 + seg];
            }
#pragma unroll
            for (int it = 0; it < 2; it++) {
                int e = tid + it * 256;       // 0..511
                int d = e >> 3, seg = e & 7;  // 64 d-rows, 8 segs of 8 keys
                uint32_t soff = (uint32_t)(d * VROWB + seg * 16);
                size_t gi = (((size_t)(bh * HDIM + d) * SEQ + j0) >> 3) + seg;
                *(uint4*)(smem + AVH_OFF + soff) = ((const uint4*)g_vhi)[gi];
            }
            if (tid < 64)
                *(float*)(smem + ABIAS_OFF + tid * 4) =
                    (mask[b * SEQ + j0 + tid] == 0) ? NEG_INF_F : 0.f;
        }
        __syncthreads();

        // ---- scores: 8 n-frags x 4 k-steps x 3 terms ----
        float sc[8][4];
#pragma unroll
        for (int i = 0; i < 8; i++)
#pragma unroll
            for (int c = 0; c < 4; c++) sc[i][c] = 0.f;

#pragma unroll
        for (int ks = 0; ks < 4; ks++) {
            uint32_t qh[4], ql[4];
            ldm_x4(qh, a_base + AQH_OFF + ks * 32);
            ldm_x4(ql, a_base + AQL_OFF + ks * 32);
#pragma unroll
            for (int np = 0; np < 4; np++) {
                uint32_t kh[4], kl[4];
                ldm_x4(kh, b_base + ks * 32 + np * 16 * ROWB);
                ldm_x4(kl, b_base + (AKL_OFF - AKH_OFF) + ks * 32 + np * 16 * ROWB);
                mma16816(sc[2 * np],     qh, kh);
                mma16816(sc[2 * np + 1], qh, kh + 2);
                mma16816(sc[2 * np],     qh, kl);
                mma16816(sc[2 * np + 1], qh, kl + 2);
                mma16816(sc[2 * np],     ql, kh);
                mma16816(sc[2 * np + 1], ql, kh + 2);
            }
        }

        // ---- pad-mask bias + causal (near-diagonal blocks only) ----
#pragma unroll
        for (int nf = 0; nf < 8; nf++) {
            float2 bv = *(const float2*)(smem + ABIAS_OFF + (nf * 8 + ec) * 4);
            sc[nf][0] += bv.x; sc[nf][1] += bv.y;
            sc[nf][2] += bv.x; sc[nf][3] += bv.y;
        }
        if (kb >= 2 * qb) {                    // block may cross the diagonal
            int rl0 = q0 + r0 + er, rl1 = rl0 + 8;
#pragma unroll
            for (int nf = 0; nf < 8; nf++) {
                int c0 = j0 + nf * 8 + ec, c1 = c0 + 1;
                if (c0 > rl0) sc[nf][0] = NEG_INF_F;
                if (c1 > rl0) sc[nf][1] = NEG_INF_F;
                if (c0 > rl1) sc[nf][2] = NEG_INF_F;
                if (c1 > rl1) sc[nf][3] = NEG_INF_F;
            }
        }

        // ---- online softmax (rows er / er+8; reduce over lane quads) ----
#pragma unroll
        for (int rr = 0; rr < 2; rr++) {
            float bm = -1e30f;
#pragma unroll
            for (int nf = 0; nf < 8; nf++)
                bm = fmaxf(bm, fmaxf(sc[nf][rr * 2], sc[nf][rr * 2 + 1]));
            bm = fmaxf(bm, __shfl_xor_sync(0xffffffffu, bm, 1));
            bm = fmaxf(bm, __shfl_xor_sync(0xffffffffu, bm, 2));
            float m_new = fmaxf(fmaxf(m_s[rr], bm), -1e29f);
            float alpha = __expf(m_s[rr] - m_new);
            float ls = 0.f;
#pragma unroll
            for (int nf = 0; nf < 8; nf++) {
                float p0 = __expf(sc[nf][rr * 2]     - m_new);
                float p1 = __expf(sc[nf][rr * 2 + 1] - m_new);
                sc[nf][rr * 2] = p0; sc[nf][rr * 2 + 1] = p1;
                ls += p0 + p1;
            }
            ls += __shfl_xor_sync(0xffffffffu, ls, 1);
            ls += __shfl_xor_sync(0xffffffffu, ls, 2);
            l_s[rr] = l_s[rr] * alpha + ls;
            m_s[rr] = m_new;
#pragma unroll
            for (int nf = 0; nf < 8; nf++) {
                o[nf][rr * 2] *= alpha; o[nf][rr * 2 + 1] *= alpha;
            }
        }

        // ---- PV: P hi/lo (regs) x Vh(T): P*Vh exactly ----
#pragma unroll
        for (int ks = 0; ks < 4; ks++) {
            uint32_t ah[4], al[4];
            ah[0] = cvt_f16x2(sc[2 * ks][1], sc[2 * ks][0]);
            ah[1] = cvt_f16x2(sc[2 * ks][3], sc[2 * ks][2]);
            ah[2] = cvt_f16x2(sc[2 * ks + 1][1], sc[2 * ks + 1][0]);
            ah[3] = cvt_f16x2(sc[2 * ks + 1][3], sc[2 * ks + 1][2]);
            al[0] = cvt_f16x2(sc[2 * ks][1] - f16x2_hi(ah[0]),
                              sc[2 * ks][0] - f16x2_lo(ah[0]));
            al[1] = cvt_f16x2(sc[2 * ks][3] - f16x2_hi(ah[1]),
                              sc[2 * ks][2] - f16x2_lo(ah[1]));
            al[2] = cvt_f16x2(sc[2 * ks + 1][1] - f16x2_hi(ah[2]),
                              sc[2 * ks + 1][0] - f16x2_lo(ah[2]));
            al[3] = cvt_f16x2(sc[2 * ks + 1][3] - f16x2_hi(ah[3]),
                              sc[2 * ks + 1][2] - f16x2_lo(ah[3]));
#pragma unroll
            for (int np = 0; np < 4; np++) {
                uint32_t vh[4];
                ldm_x4(vh, v_base + ks * 32 + np * 16 * VROWB);
                mma16816(o[2 * np],     ah, vh);
                mma16816(o[2 * np + 1], ah, vh + 2);
                mma16816(o[2 * np],     al, vh);
                mma16816(o[2 * np + 1], al, vh + 2);
            }
        }
        __syncthreads();
    }

    // ---- epilogue: normalize, split to fp16 hi/lo, store (B,S,D) ----
#pragma unroll
    for (int rr = 0; rr < 2; rr++) {
        float inv = 1.f / l_s[rr];
        int row = q0 + r0 + er + rr * 8;
        size_t base = ((size_t)b * SEQ + row) * DMODEL + h * HDIM;
#pragma unroll
        for (int nf = 0; nf < 8; nf++) {
            int d = nf * 8 + ec;
            float v0 = o[nf][rr * 2] * inv;
            float v1 = o[nf][rr * 2 + 1] * inv;
            __half2 hh;
            hh.x = __float2half_rn(v0);
            hh.y = __float2half_rn(v1);
            __half2 ll;
            ll.x = __float2half_rn(v0 - __half2float(hh.x));
            ll.y = __float2half_rn(v1 - __half2float(hh.y));
            *(__half2*)(g_ahi + base + d) = hh;
            *(__half2*)(g_alo + base + d) = ll;
        }
    }
}

// ---------------------------------------------------------------------------
// Entry point
// ---------------------------------------------------------------------------
extern "C" void kernel_launch(void* const* d_in, const int* in_sizes, int n_in,
                              void* d_out, int out_size)
{
    const float* x      = (const float*)d_in[0];   // (4, 2048, 1024) fp32
    const int*   mask   = (const int*)d_in[1];     // (4, 2048) int32
    const float* w_qkv  = (const float*)d_in[2];   // (1024, 3072) fp32
    const float* w_out  = (const float*)d_in[3];   // (1024, 1024) fp32
    float*       out    = (float*)d_out;           // (4, 2048, 1024) fp32

    (void)in_sizes; (void)n_in; (void)out_size;

    cudaFuncSetAttribute(mma_gemm_kernel<0>,
                         cudaFuncAttributeMaxDynamicSharedMemorySize, GEMM_SMEM_BYTES);
    cudaFuncSetAttribute(mma_gemm_kernel<1>,
                         cudaFuncAttributeMaxDynamicSharedMemorySize, GEMM_SMEM_BYTES);
    cudaFuncSetAttribute(flash_attn_mma_kernel,
                         cudaFuncAttributeMaxDynamicSharedMemorySize, ATT_SMEM);

    // prep: weight transposes only (x-split is fused into the QKV GEMM)
    transpose_split_kernel<<<dim3(NQKV / 32, DMODEL / 32), dim3(32, 8)>>>(w_qkv, 0, NQKV);
    transpose_split_kernel<<<dim3(DMODEL / 32, DMODEL / 32), dim3(32, 8)>>>(w_out, 1, DMODEL);

    // 1) QKV projection (fused x split) -> q/k hi/lo [bh][s][d], v hi [bh][d][s]
    mma_gemm_kernel<0><<<dim3(NQKV / 128, MROWS / 128), 256, GEMM_SMEM_BYTES>>>(x, nullptr);

    // 2) Tensorized causal flash attention (heavy-first, 2 CTA/SM) -> g_ahi/g_alo
    flash_attn_mma_kernel<<<dim3(BATCH * NHEADS, SEQ / 128), 256, ATT_SMEM>>>(mask);

    // 3) Output projection -> d_out
    mma_gemm_kernel<1><<<dim3(DMODEL / 128, MROWS / 128), 256, GEMM_SMEM_BYTES>>>(nullptr, out);
}